// round 12
// baseline (speedup 1.0000x reference)
#include <cuda_runtime.h>
#include <cuda_bf16.h>
#include <cuda_fp8.h>
#include <cstdint>

// q [75,640,441] f32, S [5,640,2205] f32 -> sim [15,5] ++ tks [15,5,5] (450 f32)
// FP8 e4m3: operands = 4 * normalized vectors; descale 1/16 at chunk merge.

#define EPSF 1e-8f
#define NEGINF (-1e30f)

// ---------------- device scratch ----------------
__device__ __align__(16) uint8_t g_qt[75 * 441 * 640];   // e4m3, [b][x][c]
__device__ __align__(16) uint8_t g_st[5 * 2205 * 640];   // e4m3, [n][m][c]
__device__ float g_isum[75 * 5];
__device__ float g_csum[75 * 5 * 5];

// ---------------- helpers ----------------
__device__ __forceinline__ uint32_t smem_u32(const void* p) {
    uint32_t a;
    asm("{ .reg .u64 t; cvta.to.shared.u64 t, %1; cvt.u32.u64 %0, t; }" : "=r"(a) : "l"(p));
    return a;
}
__device__ __forceinline__ uint32_t swz(uint32_t x) { return x ^ ((x >> 3) & 0x70); }

__device__ __forceinline__ void top3(float v, float& t0, float& t1, float& t2) {
    float b1 = fminf(t0, v);
    t0 = fmaxf(t0, v);
    float b2 = fminf(t1, b1);
    t1 = fmaxf(t1, b1);
    t2 = fmaxf(t2, b2);
}

#define CP16(dst, src) \
    asm volatile("cp.async.cg.shared.global [%0], [%1], 16;" :: "r"(dst), "l"(src) : "memory")
#define CP_MBAR_ARRIVE(a) \
    asm volatile("cp.async.mbarrier.arrive.noinc.shared.b64 [%0];" :: "r"(a) : "memory")
#define MBAR_INIT(a, c) \
    asm volatile("mbarrier.init.shared.b64 [%0], %1;" :: "r"(a), "r"((uint32_t)(c)) : "memory")
#define MBAR_ARRIVE(a) \
    asm volatile("mbarrier.arrive.shared.b64 _, [%0];" :: "r"(a) : "memory")
#define MBAR_WAIT(a, ph) do { \
    uint32_t _m = (a), _p = (ph), _d; \
    asm volatile("{\n\t.reg .pred p;\n\tmbarrier.try_wait.parity.acquire.cta.shared::cta.b64 p, [%1], %2;\n\tselp.b32 %0, 1, 0, p;\n\t}" \
        : "=r"(_d) : "r"(_m), "r"(_p) : "memory"); \
    if (!_d) { \
        asm volatile("{\n\t.reg .pred P1;\n\tWL_%=:\n\tmbarrier.try_wait.parity.acquire.cta.shared::cta.b64 P1, [%0], %1, 0x989680;\n\t@P1 bra.uni WD_%=;\n\tbra.uni WL_%=;\n\tWD_%=:\n\t}" \
            :: "r"(_m), "r"(_p) : "memory"); \
    } \
} while (0)

#define LDSM_X4(r0, r1, r2, r3, addr) \
    asm volatile("ldmatrix.sync.aligned.m8n8.x4.shared.b16 {%0,%1,%2,%3}, [%4];" \
        : "=r"(r0), "=r"(r1), "=r"(r2), "=r"(r3) : "r"(addr))
#define LDSM_X2(r0, r1, addr) \
    asm volatile("ldmatrix.sync.aligned.m8n8.x2.shared.b16 {%0,%1}, [%2];" \
        : "=r"(r0), "=r"(r1) : "r"(addr))

#define MMA(d, a, b0, b1) \
    asm volatile("mma.sync.aligned.m16n8k32.row.col.f32.e4m3.e4m3.f32 " \
        "{%0,%1,%2,%3}, {%4,%5,%6,%7}, {%8,%9}, {%0,%1,%2,%3};" \
        : "+f"((d)[0]), "+f"((d)[1]), "+f"((d)[2]), "+f"((d)[3]) \
        : "r"((a)[0]), "r"((a)[1]), "r"((a)[2]), "r"((a)[3]), "r"(b0), "r"(b1))

__device__ __forceinline__ uint8_t to_e4m3(float v) {
    return (uint8_t)__nv_cvt_float_to_fp8(v, __NV_SATFINITE, __NV_E4M3);
}

// ---------------- fused one-pass prep ----------------
// One CTA per (32-column block, image). Loads the [640 x 32] f32 tile once into
// smem (transposed, pad 641), computes column norms in-smem, writes
// normalized*4 e4m3 transposed output. Input read exactly once.
template <int STRIDE, int LIMIT>
__device__ __forceinline__ void prep_body(const float* __restrict__ src, uint8_t* __restrict__ dst,
                                          int x0, float* sm, float* part, float* scl) {
    const int tid = threadIdx.x;
    for (int idx = tid; idx < 640 * 32; idx += 256) {
        int c = idx >> 5, xx = idx & 31;
        int x = x0 + xx;
        float v = (x < LIMIT) ? src[c * STRIDE + x] : 0.f;
        sm[xx * 641 + c] = v;
    }
    __syncthreads();
    {
        int g = tid >> 5, xx = tid & 31;
        float s = 0.f;
        int c0 = g * 80;
#pragma unroll 8
        for (int c = c0; c < c0 + 80; c++) {
            float v = sm[xx * 641 + c];
            s += v * v;
        }
        part[g * 32 + xx] = s;
    }
    __syncthreads();
    if (tid < 32) {
        float tot = 0.f;
#pragma unroll
        for (int g = 0; g < 8; g++) tot += part[g * 32 + tid];
        scl[tid] = 4.f / (sqrtf(tot) + EPSF);   // 4x for e4m3 range
    }
    __syncthreads();
    {
        int w = tid >> 5, lane = tid & 31;
#pragma unroll
        for (int xi = 0; xi < 4; xi++) {
            int xx = w * 4 + xi;
            int x = x0 + xx;
            if (x >= LIMIT) continue;
            float sc = scl[xx];
            uint8_t* drow = dst + (size_t)x * 640;
#pragma unroll
            for (int j = 0; j < 5; j++) {
                int c0 = (lane + 32 * j) * 4;
                const float* sp = &sm[xx * 641 + c0];
                uchar4 o;
                o.x = to_e4m3(sp[0] * sc);
                o.y = to_e4m3(sp[1] * sc);
                o.z = to_e4m3(sp[2] * sc);
                o.w = to_e4m3(sp[3] * sc);
                *(uchar4*)(drow + c0) = o;
            }
        }
    }
}

static constexpr int PREP_SMEM = 32 * 641 * 4 + (256 + 32) * 4;  // 83,200

__global__ void prep_q(const float* __restrict__ q) {
    extern __shared__ float smf[];
    float* part = smf + 32 * 641;
    float* scl = part + 256;
    int b = blockIdx.y;
    prep_body<441, 441>(q + (size_t)b * 640 * 441, g_qt + (size_t)b * 441 * 640,
                        blockIdx.x * 32, smf, part, scl);
}

__global__ void prep_s(const float* __restrict__ S) {
    extern __shared__ float smf[];
    float* part = smf + 32 * 641;
    float* scl = part + 256;
    // fold sum-zeroing into first 10 blocks (covers all 375 + 1875 entries)
    if (blockIdx.x < 2) {
        int ci = (blockIdx.x * 5 + blockIdx.y) * 256 + (int)threadIdx.x;
        if (ci < 75 * 5) g_isum[ci] = 0.f;
        if (ci < 75 * 5 * 5) g_csum[ci] = 0.f;
    }
    int n = blockIdx.y;
    prep_body<2205, 2205>(S + (size_t)n * 640 * 2205, g_st + (size_t)n * 2205 * 640,
                          blockIdx.x * 32, smf, part, scl);
}

// ---------------- fused FP8 MMA GEMM + top-k ----------------
// grid (mt=7, n=5, b=75), 256 thr, 2 CTAs/SM. CTA tile 64 rows x 112 cols.
// A: 5 slabs [64 x 128B] SW128 resident. B: 4-slot mbarrier ring, produce-ahead 2.
// B slab = 112 rows x 128 B = 896 x 16B chunks (u==3 only for tid<128!).
static constexpr int SMA_OFF = 1024;
static constexpr int SMB_OFF = SMA_OFF + 5 * 8192;            // 41984
static constexpr int MRG_OFF = SMB_OFF + 4 * 14336;           // 99328
static constexpr int SMEM_TOTAL = MRG_OFF + 64 * 2 * 3 * 4;   // 100864

__global__ __launch_bounds__(256, 2) void gemm_topk() {
    extern __shared__ char smem[];
    const uint32_t sb = smem_u32(smem);
    const uint32_t MB_FULL = sb;        // 4 x 8B
    const uint32_t MB_EMPTY = sb + 32;  // 4 x 8B
    const uint32_t smA = sb + SMA_OFF;
    const uint32_t smB = sb + SMB_OFF;
    float* mrg = (float*)(smem + MRG_OFF);

    const int tid = threadIdx.x;
    const int w = tid >> 5, lane = tid & 31;
    const int wy = w >> 1, wx = w & 1;
    const int mt = blockIdx.x, n = blockIdx.y, b = blockIdx.z;
    const int mbase = mt * 64;

    const uint8_t* Ab = g_qt + (size_t)b * 441 * 640;
    const uint8_t* Bb = g_st + (size_t)n * 2205 * 640;

    if (tid == 0) {
#pragma unroll
        for (int i = 0; i < 4; i++) {
            MBAR_INIT(MB_FULL + 8 * i, 256);
            MBAR_INIT(MB_EMPTY + 8 * i, 8);
        }
    }
    if (mbase + 63 >= 441) {
        for (int a = tid; a < 5 * 64; a += 256) {
            int slab = a >> 6, row = a & 63;
            if (mbase + row >= 441) {
                uint32_t base = slab * 8192 + row * 128;
#pragma unroll
                for (int c16 = 0; c16 < 8; c16++)
                    *(uint4*)(smem + SMA_OFF + swz(base + c16 * 16)) = make_uint4(0, 0, 0, 0);
            }
        }
    }
    __syncthreads();

    // A cp.asyncs (full K, 5 slabs of [64 x 128B])
    for (int a = tid; a < 2560; a += 256) {
        int slab = a >> 9, rem = a & 511;
        int row = rem >> 3, c16 = rem & 7;
        int x = mbase + row;
        if (x < 441) {
            uint32_t dst = smA + slab * 8192 + swz(row * 128 + c16 * 16);
            CP16(dst, __cvta_generic_to_global(Ab + (size_t)x * 640 + slab * 128 + c16 * 16));
        }
    }

    // per-thread precomputed produce bases (chunk u valid iff u<3 || tid<128)
    const uint8_t* gB[4];
    uint32_t dstoff[4];
    int rowu[4];
#pragma unroll
    for (int u = 0; u < 4; u++) {
        int ci = tid + u * 256;
        int row = ci >> 3, c16 = ci & 7;
        gB[u] = Bb + (size_t)row * 640 + c16 * 16;
        dstoff[u] = swz(row * 128 + c16 * 16);
        rowu[u] = row;
    }
    const bool has4 = (tid < 128);  // 896 chunks total: u==3 only for tid<128

    // produce B slab g into slot g%4
    auto produce = [&](int g) {
        if (g >= 100) return;
        if (g >= 4) MBAR_WAIT(MB_EMPTY + 8 * (g & 3), ((g >> 2) + 1) & 1);
        int T = g / 5, k = g - T * 5;
        int m0 = (T >> 2) * 441 + (T & 3) * 112;
        uint64_t goff = (uint64_t)m0 * 640 + (uint32_t)(k * 128);
        uint32_t slot = smB + (uint32_t)(g & 3) * 14336;
        if (g < 95) {
#pragma unroll
            for (int u = 0; u < 4; u++)
                if (u < 3 || has4)
                    CP16(slot + dstoff[u], __cvta_generic_to_global(gB[u] + goff));
        } else {
#pragma unroll
            for (int u = 0; u < 4; u++)
                if ((u < 3 || has4) && m0 + rowu[u] < 2205)
                    CP16(slot + dstoff[u], __cvta_generic_to_global(gB[u] + goff));
        }
        CP_MBAR_ARRIVE(MB_FULL + 8 * (g & 3));
    };

    produce(0); produce(1);   // produce-ahead 2

    // precomputed swizzled fragment offsets (slab-relative)
    uint32_t aoff[4], boff[4][3], boff2[4];
    {
        int blk = lane >> 3;
#pragma unroll
        for (int kk = 0; kk < 4; kk++) {
            {
                int row = wy * 16 + (lane & 15);
                aoff[kk] = swz(row * 128 + kk * 32 + (lane >> 4) * 16);
            }
#pragma unroll
            for (int tp = 0; tp < 3; tp++) {
                int nrow = wx * 56 + tp * 16 + (blk >> 1) * 8 + (lane & 7);
                boff[kk][tp] = swz(nrow * 128 + kk * 32 + (blk & 1) * 16);
            }
            {
                int nrow = wx * 56 + 48 + (lane & 7);
                boff2[kk] = swz(nrow * 128 + kk * 32 + ((lane >> 3) & 1) * 16);
            }
        }
    }

    float gt0 = NEGINF, gt1 = NEGINF, gt2 = NEGINF;
    int cc = 0;

    uint32_t bfr[2][14];
    auto loadB = [&](uint32_t bS, int kk, int p) {
#pragma unroll
        for (int tp = 0; tp < 3; tp++)
            LDSM_X4(bfr[p][tp * 4 + 0], bfr[p][tp * 4 + 1], bfr[p][tp * 4 + 2], bfr[p][tp * 4 + 3],
                    bS + boff[kk][tp]);
        LDSM_X2(bfr[p][12], bfr[p][13], bS + boff2[kk]);
    };

    for (int s = 0; s < 5; s++) {
        float tri[2][3];  // [half][3] chunk top3 (raw, undescaled)
#pragma unroll
        for (int h = 0; h < 2; h++) { tri[h][0] = NEGINF; tri[h][1] = NEGINF; tri[h][2] = NEGINF; }

#pragma unroll
        for (int nt = 0; nt < 4; nt++) {
            float acc[7][4];
#pragma unroll
            for (int t = 0; t < 7; t++)
#pragma unroll
                for (int e = 0; e < 4; e++) acc[t][e] = 0.f;

            for (int k = 0; k < 5; k++, cc++) {
                produce(cc + 2);
                MBAR_WAIT(MB_FULL + 8 * (cc & 3), (cc >> 2) & 1);

                uint32_t aS = smA + k * 8192;
                uint32_t bS = smB + (uint32_t)(cc & 3) * 14336;

                uint32_t afr[2][4];   // double-buffered A fragments
                LDSM_X4(afr[0][0], afr[0][1], afr[0][2], afr[0][3], aS + aoff[0]);
                loadB(bS, 0, 0);
#pragma unroll
                for (int kk = 0; kk < 4; kk++) {
                    const int p = kk & 1;
                    if (kk < 3) {
                        LDSM_X4(afr[p ^ 1][0], afr[p ^ 1][1], afr[p ^ 1][2], afr[p ^ 1][3],
                                aS + aoff[kk + 1]);
                        loadB(bS, kk + 1, p ^ 1);
                    }
#pragma unroll
                    for (int tp = 0; tp < 3; tp++) {
                        MMA(acc[2 * tp],     afr[p], bfr[p][4 * tp],     bfr[p][4 * tp + 1]);
                        MMA(acc[2 * tp + 1], afr[p], bfr[p][4 * tp + 2], bfr[p][4 * tp + 3]);
                    }
                    MMA(acc[6], afr[p], bfr[p][12], bfr[p][13]);
                }
                if (lane == 0) MBAR_ARRIVE(MB_EMPTY + 8 * (cc & 3));
            }

            // ntile epilogue: masked top3 on RAW accs (guards vanish for nt<3)
            int colbase = nt * 112 + wx * 56 + (lane & 3) * 2;
#pragma unroll
            for (int t = 0; t < 7; t++) {
                int c0 = colbase + t * 8;
                if (nt < 3 || c0 < 441) {
                    top3(acc[t][0], tri[0][0], tri[0][1], tri[0][2]);
                    top3(acc[t][2], tri[1][0], tri[1][1], tri[1][2]);
                }
                if (nt < 3 || c0 + 1 < 441) {
                    top3(acc[t][1], tri[0][0], tri[0][1], tri[0][2]);
                    top3(acc[t][3], tri[1][0], tri[1][1], tri[1][2]);
                }
            }
        }  // nt

        // chunk merge across lane%4
#pragma unroll
        for (int h = 0; h < 2; h++)
#pragma unroll
            for (int ofs = 1; ofs <= 2; ofs <<= 1) {
                float o0 = __shfl_xor_sync(0xFFFFFFFFu, tri[h][0], ofs);
                float o1 = __shfl_xor_sync(0xFFFFFFFFu, tri[h][1], ofs);
                float o2 = __shfl_xor_sync(0xFFFFFFFFu, tri[h][2], ofs);
                top3(o0, tri[h][0], tri[h][1], tri[h][2]);
                top3(o1, tri[h][0], tri[h][1], tri[h][2]);
                top3(o2, tri[h][0], tri[h][1], tri[h][2]);
            }
        if ((lane & 3) == 0) {
#pragma unroll
            for (int h = 0; h < 2; h++) {
                int row = wy * 16 + h * 8 + (lane >> 2);
                float* p = &mrg[(row * 2 + wx) * 3];
                p[0] = tri[h][0] * 0.0625f;   // descale here (1/16)
                p[1] = tri[h][1] * 0.0625f;
                p[2] = tri[h][2] * 0.0625f;
            }
        }
        __syncthreads();
        if (tid < 64) {
            float c0 = mrg[(tid * 2) * 3], c1 = mrg[(tid * 2) * 3 + 1], c2 = mrg[(tid * 2) * 3 + 2];
            top3(mrg[(tid * 2 + 1) * 3],     c0, c1, c2);
            top3(mrg[(tid * 2 + 1) * 3 + 1], c0, c1, c2);
            top3(mrg[(tid * 2 + 1) * 3 + 2], c0, c1, c2);
            bool valid = (mbase + tid) < 441;
            float cs = valid ? (c0 + c1 + c2) : 0.f;
#pragma unroll
            for (int o = 16; o; o >>= 1) cs += __shfl_xor_sync(0xFFFFFFFFu, cs, o);
            if (lane == 0) atomicAdd(&g_csum[(b * 5 + n) * 5 + s], cs);
            top3(c0, gt0, gt1, gt2);
            top3(c1, gt0, gt1, gt2);
            top3(c2, gt0, gt1, gt2);
        }
        __syncthreads();
    }  // chunks

    if (tid < 64) {
        bool valid = (mbase + tid) < 441;
        float gs = valid ? (gt0 + gt1 + gt2) : 0.f;
#pragma unroll
        for (int o = 16; o; o >>= 1) gs += __shfl_xor_sync(0xFFFFFFFFu, gs, o);
        if (lane == 0) atomicAdd(&g_isum[b * 5 + n], gs);
    }
}

// ---------------- finalize ----------------
__global__ void finalize_kernel(float* __restrict__ out) {
    int t = threadIdx.x;
    if (t < 75) {
        int g = t / 5, n = t % 5;
        float acc = 0.f;
        for (int a = 0; a < 5; a++) acc += logf(g_isum[(g * 5 + a) * 5 + n]);
        out[t] = expf(acc * 0.2f);
    }
    if (t < 375) {
        int g = t / 25, rem = t % 25, n = rem / 5, s = rem % 5;
        float acc = 0.f;
        for (int a = 0; a < 5; a++)
            acc += logf(fmaxf(g_csum[((g * 5 + a) * 5 + n) * 5 + s], 1e-8f));
        out[75 + t] = expf(acc * 0.2f);
    }
}

// ---------------- host ----------------
extern "C" void kernel_launch(void* const* d_in, const int* in_sizes, int n_in,
                              void* d_out, int out_size) {
    const float* q = (const float*)d_in[0];
    const float* S = (const float*)d_in[1];
    float* out = (float*)d_out;

    cudaFuncSetAttribute(prep_q, cudaFuncAttributeMaxDynamicSharedMemorySize, PREP_SMEM);
    cudaFuncSetAttribute(prep_s, cudaFuncAttributeMaxDynamicSharedMemorySize, PREP_SMEM);

    prep_s<<<dim3(69, 5), 256, PREP_SMEM>>>(S);    // #1 (also zeroes sums)
    prep_q<<<dim3(14, 75), 256, PREP_SMEM>>>(q);   // #2

    cudaFuncSetAttribute(gemm_topk, cudaFuncAttributeMaxDynamicSharedMemorySize, SMEM_TOTAL);
    gemm_topk<<<dim3(7, 5, 75), 256, SMEM_TOTAL>>>();  // #3 (profiled)

    finalize_kernel<<<1, 512>>>(out);              // #4
}

// round 13
// speedup vs baseline: 1.0111x; 1.0111x over previous
#include <cuda_runtime.h>
#include <cuda_bf16.h>
#include <cuda_fp16.h>
#include <cuda_fp8.h>
#include <cstdint>

// q [75,640,441] f32, S [5,640,2205] f32 -> sim [15,5] ++ tks [15,5,5] (450 f32)
// FP8 e4m3: operands = 4 * normalized vectors; descale 1/16 at chunk merge.
// Top-3 tracking in packed fp16x2 (rows r / r+8 share a lane pair).

#define EPSF 1e-8f
#define NEGINF (-1e30f)

// ---------------- device scratch ----------------
__device__ __align__(16) uint8_t g_qt[75 * 441 * 640];   // e4m3, [b][x][c]
__device__ __align__(16) uint8_t g_st[5 * 2205 * 640];   // e4m3, [n][m][c]
__device__ float g_isum[75 * 5];
__device__ float g_csum[75 * 5 * 5];

// ---------------- helpers ----------------
__device__ __forceinline__ uint32_t smem_u32(const void* p) {
    uint32_t a;
    asm("{ .reg .u64 t; cvta.to.shared.u64 t, %1; cvt.u32.u64 %0, t; }" : "=r"(a) : "l"(p));
    return a;
}
__device__ __forceinline__ uint32_t swz(uint32_t x) { return x ^ ((x >> 3) & 0x70); }

__device__ __forceinline__ void top3(float v, float& t0, float& t1, float& t2) {
    float b1 = fminf(t0, v);
    t0 = fmaxf(t0, v);
    float b2 = fminf(t1, b1);
    t1 = fmaxf(t1, b1);
    t2 = fmaxf(t2, b2);
}

// packed half2 top-3 insertion (lane-wise), sorted t0>=t1>=t2
__device__ __forceinline__ void top3h(__half2 v, __half2& t0, __half2& t1, __half2& t2) {
    __half2 b1 = __hmin2(t0, v);
    t0 = __hmax2(t0, v);
    __half2 b2 = __hmin2(t1, b1);
    t1 = __hmax2(t1, b1);
    t2 = __hmax2(t2, b2);
}

#define CP16(dst, src) \
    asm volatile("cp.async.cg.shared.global [%0], [%1], 16;" :: "r"(dst), "l"(src) : "memory")
#define CP_MBAR_ARRIVE(a) \
    asm volatile("cp.async.mbarrier.arrive.noinc.shared.b64 [%0];" :: "r"(a) : "memory")
#define MBAR_INIT(a, c) \
    asm volatile("mbarrier.init.shared.b64 [%0], %1;" :: "r"(a), "r"((uint32_t)(c)) : "memory")
#define MBAR_ARRIVE(a) \
    asm volatile("mbarrier.arrive.shared.b64 _, [%0];" :: "r"(a) : "memory")
#define MBAR_WAIT(a, ph) do { \
    uint32_t _m = (a), _p = (ph), _d; \
    asm volatile("{\n\t.reg .pred p;\n\tmbarrier.try_wait.parity.acquire.cta.shared::cta.b64 p, [%1], %2;\n\tselp.b32 %0, 1, 0, p;\n\t}" \
        : "=r"(_d) : "r"(_m), "r"(_p) : "memory"); \
    if (!_d) { \
        asm volatile("{\n\t.reg .pred P1;\n\tWL_%=:\n\tmbarrier.try_wait.parity.acquire.cta.shared::cta.b64 P1, [%0], %1, 0x989680;\n\t@P1 bra.uni WD_%=;\n\tbra.uni WL_%=;\n\tWD_%=:\n\t}" \
            :: "r"(_m), "r"(_p) : "memory"); \
    } \
} while (0)

#define LDSM_X4(r0, r1, r2, r3, addr) \
    asm volatile("ldmatrix.sync.aligned.m8n8.x4.shared.b16 {%0,%1,%2,%3}, [%4];" \
        : "=r"(r0), "=r"(r1), "=r"(r2), "=r"(r3) : "r"(addr))
#define LDSM_X2(r0, r1, addr) \
    asm volatile("ldmatrix.sync.aligned.m8n8.x2.shared.b16 {%0,%1}, [%2];" \
        : "=r"(r0), "=r"(r1) : "r"(addr))

#define MMA(d, a, b0, b1) \
    asm volatile("mma.sync.aligned.m16n8k32.row.col.f32.e4m3.e4m3.f32 " \
        "{%0,%1,%2,%3}, {%4,%5,%6,%7}, {%8,%9}, {%0,%1,%2,%3};" \
        : "+f"((d)[0]), "+f"((d)[1]), "+f"((d)[2]), "+f"((d)[3]) \
        : "r"((a)[0]), "r"((a)[1]), "r"((a)[2]), "r"((a)[3]), "r"(b0), "r"(b1))

__device__ __forceinline__ uint8_t to_e4m3(float v) {
    return (uint8_t)__nv_cvt_float_to_fp8(v, __NV_SATFINITE, __NV_E4M3);
}

// ---------------- fused one-pass prep ----------------
template <int STRIDE, int LIMIT>
__device__ __forceinline__ void prep_body(const float* __restrict__ src, uint8_t* __restrict__ dst,
                                          int x0, float* sm, float* part, float* scl) {
    const int tid = threadIdx.x;
    for (int idx = tid; idx < 640 * 32; idx += 256) {
        int c = idx >> 5, xx = idx & 31;
        int x = x0 + xx;
        float v = (x < LIMIT) ? src[c * STRIDE + x] : 0.f;
        sm[xx * 641 + c] = v;
    }
    __syncthreads();
    {
        int g = tid >> 5, xx = tid & 31;
        float s = 0.f;
        int c0 = g * 80;
#pragma unroll 8
        for (int c = c0; c < c0 + 80; c++) {
            float v = sm[xx * 641 + c];
            s += v * v;
        }
        part[g * 32 + xx] = s;
    }
    __syncthreads();
    if (tid < 32) {
        float tot = 0.f;
#pragma unroll
        for (int g = 0; g < 8; g++) tot += part[g * 32 + tid];
        scl[tid] = 4.f / (sqrtf(tot) + EPSF);   // 4x for e4m3 range
    }
    __syncthreads();
    {
        int w = tid >> 5, lane = tid & 31;
#pragma unroll
        for (int xi = 0; xi < 4; xi++) {
            int xx = w * 4 + xi;
            int x = x0 + xx;
            if (x >= LIMIT) continue;
            float sc = scl[xx];
            uint8_t* drow = dst + (size_t)x * 640;
#pragma unroll
            for (int j = 0; j < 5; j++) {
                int c0 = (lane + 32 * j) * 4;
                const float* sp = &sm[xx * 641 + c0];
                uchar4 o;
                o.x = to_e4m3(sp[0] * sc);
                o.y = to_e4m3(sp[1] * sc);
                o.z = to_e4m3(sp[2] * sc);
                o.w = to_e4m3(sp[3] * sc);
                *(uchar4*)(drow + c0) = o;
            }
        }
    }
}

static constexpr int PREP_SMEM = 32 * 641 * 4 + (256 + 32) * 4;  // 83,200

__global__ void prep_q(const float* __restrict__ q) {
    extern __shared__ float smf[];
    float* part = smf + 32 * 641;
    float* scl = part + 256;
    int b = blockIdx.y;
    prep_body<441, 441>(q + (size_t)b * 640 * 441, g_qt + (size_t)b * 441 * 640,
                        blockIdx.x * 32, smf, part, scl);
}

__global__ void prep_s(const float* __restrict__ S) {
    extern __shared__ float smf[];
    float* part = smf + 32 * 641;
    float* scl = part + 256;
    if (blockIdx.x < 2) {
        int ci = (blockIdx.x * 5 + blockIdx.y) * 256 + (int)threadIdx.x;
        if (ci < 75 * 5) g_isum[ci] = 0.f;
        if (ci < 75 * 5 * 5) g_csum[ci] = 0.f;
    }
    int n = blockIdx.y;
    prep_body<2205, 2205>(S + (size_t)n * 640 * 2205, g_st + (size_t)n * 2205 * 640,
                          blockIdx.x * 32, smf, part, scl);
}

// ---------------- fused FP8 MMA GEMM + top-k ----------------
// grid (mt=7, n=5, b=75), 256 thr, 2 CTAs/SM. CTA tile 64 rows x 112 cols.
// A: 5 slabs [64 x 128B] SW128 resident. B: 4-slot mbarrier ring, produce-ahead 2.
// B slab = 112 rows x 128 B = 896 x 16B chunks (u==3 only for tid<128).
static constexpr int SMA_OFF = 1024;
static constexpr int SMB_OFF = SMA_OFF + 5 * 8192;            // 41984
static constexpr int MRG_OFF = SMB_OFF + 4 * 14336;           // 99328
static constexpr int SMEM_TOTAL = MRG_OFF + 64 * 2 * 3 * 4;   // 100864

__global__ __launch_bounds__(256, 2) void gemm_topk() {
    extern __shared__ char smem[];
    const uint32_t sb = smem_u32(smem);
    const uint32_t MB_FULL = sb;        // 4 x 8B
    const uint32_t MB_EMPTY = sb + 32;  // 4 x 8B
    const uint32_t smA = sb + SMA_OFF;
    const uint32_t smB = sb + SMB_OFF;
    float* mrg = (float*)(smem + MRG_OFF);

    const int tid = threadIdx.x;
    const int w = tid >> 5, lane = tid & 31;
    const int wy = w >> 1, wx = w & 1;
    const int mt = blockIdx.x, n = blockIdx.y, b = blockIdx.z;
    const int mbase = mt * 64;

    const uint8_t* Ab = g_qt + (size_t)b * 441 * 640;
    const uint8_t* Bb = g_st + (size_t)n * 2205 * 640;

    if (tid == 0) {
#pragma unroll
        for (int i = 0; i < 4; i++) {
            MBAR_INIT(MB_FULL + 8 * i, 256);
            MBAR_INIT(MB_EMPTY + 8 * i, 8);
        }
    }
    if (mbase + 63 >= 441) {
        for (int a = tid; a < 5 * 64; a += 256) {
            int slab = a >> 6, row = a & 63;
            if (mbase + row >= 441) {
                uint32_t base = slab * 8192 + row * 128;
#pragma unroll
                for (int c16 = 0; c16 < 8; c16++)
                    *(uint4*)(smem + SMA_OFF + swz(base + c16 * 16)) = make_uint4(0, 0, 0, 0);
            }
        }
    }
    __syncthreads();

    // A cp.asyncs (full K, 5 slabs of [64 x 128B])
    for (int a = tid; a < 2560; a += 256) {
        int slab = a >> 9, rem = a & 511;
        int row = rem >> 3, c16 = rem & 7;
        int x = mbase + row;
        if (x < 441) {
            uint32_t dst = smA + slab * 8192 + swz(row * 128 + c16 * 16);
            CP16(dst, __cvta_generic_to_global(Ab + (size_t)x * 640 + slab * 128 + c16 * 16));
        }
    }

    // per-thread precomputed produce bases (chunk u valid iff u<3 || tid<128)
    const uint8_t* gB[4];
    uint32_t dstoff[4];
    int rowu[4];
#pragma unroll
    for (int u = 0; u < 4; u++) {
        int ci = tid + u * 256;
        int row = ci >> 3, c16 = ci & 7;
        gB[u] = Bb + (size_t)row * 640 + c16 * 16;
        dstoff[u] = swz(row * 128 + c16 * 16);
        rowu[u] = row;
    }
    const bool has4 = (tid < 128);

    // produce B slab g into slot g%4
    auto produce = [&](int g) {
        if (g >= 100) return;
        if (g >= 4) MBAR_WAIT(MB_EMPTY + 8 * (g & 3), ((g >> 2) + 1) & 1);
        int T = g / 5, k = g - T * 5;
        int m0 = (T >> 2) * 441 + (T & 3) * 112;
        uint64_t goff = (uint64_t)m0 * 640 + (uint32_t)(k * 128);
        uint32_t slot = smB + (uint32_t)(g & 3) * 14336;
        if (g < 95) {
#pragma unroll
            for (int u = 0; u < 4; u++)
                if (u < 3 || has4)
                    CP16(slot + dstoff[u], __cvta_generic_to_global(gB[u] + goff));
        } else {
#pragma unroll
            for (int u = 0; u < 4; u++)
                if ((u < 3 || has4) && m0 + rowu[u] < 2205)
                    CP16(slot + dstoff[u], __cvta_generic_to_global(gB[u] + goff));
        }
        CP_MBAR_ARRIVE(MB_FULL + 8 * (g & 3));
    };

    produce(0); produce(1);   // produce-ahead 2

    // precomputed swizzled fragment offsets (slab-relative)
    uint32_t aoff[4], boff[4][3], boff2[4];
    {
        int blk = lane >> 3;
#pragma unroll
        for (int kk = 0; kk < 4; kk++) {
            {
                int row = wy * 16 + (lane & 15);
                aoff[kk] = swz(row * 128 + kk * 32 + (lane >> 4) * 16);
            }
#pragma unroll
            for (int tp = 0; tp < 3; tp++) {
                int nrow = wx * 56 + tp * 16 + (blk >> 1) * 8 + (lane & 7);
                boff[kk][tp] = swz(nrow * 128 + kk * 32 + (blk & 1) * 16);
            }
            {
                int nrow = wx * 56 + 48 + (lane & 7);
                boff2[kk] = swz(nrow * 128 + kk * 32 + ((lane >> 3) & 1) * 16);
            }
        }
    }

    float gt0 = NEGINF, gt1 = NEGINF, gt2 = NEGINF;
    int cc = 0;

    uint32_t bfr[2][14];
    auto loadB = [&](uint32_t bS, int kk, int p) {
#pragma unroll
        for (int tp = 0; tp < 3; tp++)
            LDSM_X4(bfr[p][tp * 4 + 0], bfr[p][tp * 4 + 1], bfr[p][tp * 4 + 2], bfr[p][tp * 4 + 3],
                    bS + boff[kk][tp]);
        LDSM_X2(bfr[p][12], bfr[p][13], bS + boff2[kk]);
    };

    const __half2 NEGH = __float2half2_rn(-60000.f);

    for (int s = 0; s < 5; s++) {
        // packed chunk top3: lane.x = row (wy*16 + lane>>2), lane.y = row+8
        __half2 tp0 = NEGH, tp1 = NEGH, tp2 = NEGH;

#pragma unroll
        for (int nt = 0; nt < 4; nt++) {
            float acc[7][4];
#pragma unroll
            for (int t = 0; t < 7; t++)
#pragma unroll
                for (int e = 0; e < 4; e++) acc[t][e] = 0.f;

            for (int k = 0; k < 5; k++, cc++) {
                produce(cc + 2);
                MBAR_WAIT(MB_FULL + 8 * (cc & 3), (cc >> 2) & 1);

                uint32_t aS = smA + k * 8192;
                uint32_t bS = smB + (uint32_t)(cc & 3) * 14336;

                uint32_t afr[2][4];   // double-buffered A fragments
                LDSM_X4(afr[0][0], afr[0][1], afr[0][2], afr[0][3], aS + aoff[0]);
                loadB(bS, 0, 0);
#pragma unroll
                for (int kk = 0; kk < 4; kk++) {
                    const int p = kk & 1;
                    if (kk < 3) {
                        LDSM_X4(afr[p ^ 1][0], afr[p ^ 1][1], afr[p ^ 1][2], afr[p ^ 1][3],
                                aS + aoff[kk + 1]);
                        loadB(bS, kk + 1, p ^ 1);
                    }
#pragma unroll
                    for (int tp = 0; tp < 3; tp++) {
                        MMA(acc[2 * tp],     afr[p], bfr[p][4 * tp],     bfr[p][4 * tp + 1]);
                        MMA(acc[2 * tp + 1], afr[p], bfr[p][4 * tp + 2], bfr[p][4 * tp + 3]);
                    }
                    MMA(acc[6], afr[p], bfr[p][12], bfr[p][13]);
                }
                if (lane == 0) MBAR_ARRIVE(MB_EMPTY + 8 * (cc & 3));
            }

            // ntile epilogue: packed fp16x2 top3 (pair = same col, rows r / r+8)
            int colbase = nt * 112 + wx * 56 + (lane & 3) * 2;
#pragma unroll
            for (int t = 0; t < 7; t++) {
                int c0 = colbase + t * 8;
                if (nt < 3 || c0 < 441)
                    top3h(__floats2half2_rn(acc[t][0], acc[t][2]), tp0, tp1, tp2);
                if (nt < 3 || c0 + 1 < 441)
                    top3h(__floats2half2_rn(acc[t][1], acc[t][3]), tp0, tp1, tp2);
            }
        }  // nt

        // unpack to fp32 triples, then merge across lane%4 (fp32, as before)
        float tri[2][3];
        {
            float2 f0 = __half22float2(tp0);
            float2 f1 = __half22float2(tp1);
            float2 f2 = __half22float2(tp2);
            tri[0][0] = f0.x; tri[0][1] = f1.x; tri[0][2] = f2.x;
            tri[1][0] = f0.y; tri[1][1] = f1.y; tri[1][2] = f2.y;
        }
#pragma unroll
        for (int h = 0; h < 2; h++)
#pragma unroll
            for (int ofs = 1; ofs <= 2; ofs <<= 1) {
                float o0 = __shfl_xor_sync(0xFFFFFFFFu, tri[h][0], ofs);
                float o1 = __shfl_xor_sync(0xFFFFFFFFu, tri[h][1], ofs);
                float o2 = __shfl_xor_sync(0xFFFFFFFFu, tri[h][2], ofs);
                top3(o0, tri[h][0], tri[h][1], tri[h][2]);
                top3(o1, tri[h][0], tri[h][1], tri[h][2]);
                top3(o2, tri[h][0], tri[h][1], tri[h][2]);
            }
        if ((lane & 3) == 0) {
#pragma unroll
            for (int h = 0; h < 2; h++) {
                int row = wy * 16 + h * 8 + (lane >> 2);
                float* p = &mrg[(row * 2 + wx) * 3];
                p[0] = tri[h][0] * 0.0625f;   // descale here (1/16)
                p[1] = tri[h][1] * 0.0625f;
                p[2] = tri[h][2] * 0.0625f;
            }
        }
        __syncthreads();
        if (tid < 64) {
            float c0 = mrg[(tid * 2) * 3], c1 = mrg[(tid * 2) * 3 + 1], c2 = mrg[(tid * 2) * 3 + 2];
            top3(mrg[(tid * 2 + 1) * 3],     c0, c1, c2);
            top3(mrg[(tid * 2 + 1) * 3 + 1], c0, c1, c2);
            top3(mrg[(tid * 2 + 1) * 3 + 2], c0, c1, c2);
            bool valid = (mbase + tid) < 441;
            float cs = valid ? (c0 + c1 + c2) : 0.f;
#pragma unroll
            for (int o = 16; o; o >>= 1) cs += __shfl_xor_sync(0xFFFFFFFFu, cs, o);
            if (lane == 0) atomicAdd(&g_csum[(b * 5 + n) * 5 + s], cs);
            top3(c0, gt0, gt1, gt2);
            top3(c1, gt0, gt1, gt2);
            top3(c2, gt0, gt1, gt2);
        }
        __syncthreads();
    }  // chunks

    if (tid < 64) {
        bool valid = (mbase + tid) < 441;
        float gs = valid ? (gt0 + gt1 + gt2) : 0.f;
#pragma unroll
        for (int o = 16; o; o >>= 1) gs += __shfl_xor_sync(0xFFFFFFFFu, gs, o);
        if (lane == 0) atomicAdd(&g_isum[b * 5 + n], gs);
    }
}

// ---------------- finalize ----------------
__global__ void finalize_kernel(float* __restrict__ out) {
    int t = threadIdx.x;
    if (t < 75) {
        int g = t / 5, n = t % 5;
        float acc = 0.f;
        for (int a = 0; a < 5; a++) acc += logf(g_isum[(g * 5 + a) * 5 + n]);
        out[t] = expf(acc * 0.2f);
    }
    if (t < 375) {
        int g = t / 25, rem = t % 25, n = rem / 5, s = rem % 5;
        float acc = 0.f;
        for (int a = 0; a < 5; a++)
            acc += logf(fmaxf(g_csum[((g * 5 + a) * 5 + n) * 5 + s], 1e-8f));
        out[75 + t] = expf(acc * 0.2f);
    }
}

// ---------------- host ----------------
extern "C" void kernel_launch(void* const* d_in, const int* in_sizes, int n_in,
                              void* d_out, int out_size) {
    const float* q = (const float*)d_in[0];
    const float* S = (const float*)d_in[1];
    float* out = (float*)d_out;

    cudaFuncSetAttribute(prep_q, cudaFuncAttributeMaxDynamicSharedMemorySize, PREP_SMEM);
    cudaFuncSetAttribute(prep_s, cudaFuncAttributeMaxDynamicSharedMemorySize, PREP_SMEM);

    prep_s<<<dim3(69, 5), 256, PREP_SMEM>>>(S);    // #1 (also zeroes sums)
    prep_q<<<dim3(14, 75), 256, PREP_SMEM>>>(q);   // #2

    cudaFuncSetAttribute(gemm_topk, cudaFuncAttributeMaxDynamicSharedMemorySize, SMEM_TOTAL);
    gemm_topk<<<dim3(7, 5, 75), 256, SMEM_TOTAL>>>();  // #3 (profiled)

    finalize_kernel<<<1, 512>>>(out);              // #4
}

// round 14
// speedup vs baseline: 1.0192x; 1.0081x over previous
#include <cuda_runtime.h>
#include <cuda_bf16.h>
#include <cuda_fp16.h>
#include <cuda_fp8.h>
#include <cstdint>

// q [75,640,441] f32, S [5,640,2205] f32 -> sim [15,5] ++ tks [15,5,5] (450 f32)
// FP8 e4m3: operands = 4 * normalized vectors; descale 1/16 at chunk merge.
// Top-3 tracking in packed fp16x2 (rows r / r+8 share a lane pair).

#define EPSF 1e-8f
#define NEGINF (-1e30f)

// ---------------- device scratch ----------------
__device__ __align__(16) uint8_t g_qt[75 * 441 * 640];   // e4m3, [b][x][c]
__device__ __align__(16) uint8_t g_st[5 * 2205 * 640];   // e4m3, [n][m][c]
__device__ float g_isum[75 * 5];
__device__ float g_csum[75 * 5 * 5];

// ---------------- helpers ----------------
__device__ __forceinline__ uint32_t smem_u32(const void* p) {
    uint32_t a;
    asm("{ .reg .u64 t; cvta.to.shared.u64 t, %1; cvt.u32.u64 %0, t; }" : "=r"(a) : "l"(p));
    return a;
}
__device__ __forceinline__ uint32_t swz(uint32_t x) { return x ^ ((x >> 3) & 0x70); }

__device__ __forceinline__ void top3(float v, float& t0, float& t1, float& t2) {
    float b1 = fminf(t0, v);
    t0 = fmaxf(t0, v);
    float b2 = fminf(t1, b1);
    t1 = fmaxf(t1, b1);
    t2 = fmaxf(t2, b2);
}

// packed half2 top-3 insertion (lane-wise), sorted t0>=t1>=t2
__device__ __forceinline__ void top3h(__half2 v, __half2& t0, __half2& t1, __half2& t2) {
    __half2 b1 = __hmin2(t0, v);
    t0 = __hmax2(t0, v);
    __half2 b2 = __hmin2(t1, b1);
    t1 = __hmax2(t1, b1);
    t2 = __hmax2(t2, b2);
}

#define CP16(dst, src) \
    asm volatile("cp.async.cg.shared.global [%0], [%1], 16;" :: "r"(dst), "l"(src) : "memory")
#define CP_MBAR_ARRIVE(a) \
    asm volatile("cp.async.mbarrier.arrive.noinc.shared.b64 [%0];" :: "r"(a) : "memory")
#define MBAR_INIT(a, c) \
    asm volatile("mbarrier.init.shared.b64 [%0], %1;" :: "r"(a), "r"((uint32_t)(c)) : "memory")
#define MBAR_ARRIVE(a) \
    asm volatile("mbarrier.arrive.shared.b64 _, [%0];" :: "r"(a) : "memory")
#define MBAR_WAIT(a, ph) do { \
    uint32_t _m = (a), _p = (ph), _d; \
    asm volatile("{\n\t.reg .pred p;\n\tmbarrier.try_wait.parity.acquire.cta.shared::cta.b64 p, [%1], %2;\n\tselp.b32 %0, 1, 0, p;\n\t}" \
        : "=r"(_d) : "r"(_m), "r"(_p) : "memory"); \
    if (!_d) { \
        asm volatile("{\n\t.reg .pred P1;\n\tWL_%=:\n\tmbarrier.try_wait.parity.acquire.cta.shared::cta.b64 P1, [%0], %1, 0x989680;\n\t@P1 bra.uni WD_%=;\n\tbra.uni WL_%=;\n\tWD_%=:\n\t}" \
            :: "r"(_m), "r"(_p) : "memory"); \
    } \
} while (0)

// relaxed wait: producer empty-waits only (post-wait accesses are cp.async = async proxy)
#define MBAR_WAIT_RELAXED(a, ph) do { \
    uint32_t _m = (a), _p = (ph), _d; \
    asm volatile("{\n\t.reg .pred p;\n\tmbarrier.try_wait.parity.relaxed.cta.shared::cta.b64 p, [%1], %2;\n\tselp.b32 %0, 1, 0, p;\n\t}" \
        : "=r"(_d) : "r"(_m), "r"(_p) : "memory"); \
    if (!_d) { \
        asm volatile("{\n\t.reg .pred P1;\n\tWL_%=:\n\tmbarrier.try_wait.parity.relaxed.cta.shared::cta.b64 P1, [%0], %1, 0x989680;\n\t@P1 bra.uni WD_%=;\n\tbra.uni WL_%=;\n\tWD_%=:\n\t}" \
            :: "r"(_m), "r"(_p) : "memory"); \
    } \
} while (0)

#define LDSM_X4(r0, r1, r2, r3, addr) \
    asm volatile("ldmatrix.sync.aligned.m8n8.x4.shared.b16 {%0,%1,%2,%3}, [%4];" \
        : "=r"(r0), "=r"(r1), "=r"(r2), "=r"(r3) : "r"(addr))
#define LDSM_X2(r0, r1, addr) \
    asm volatile("ldmatrix.sync.aligned.m8n8.x2.shared.b16 {%0,%1}, [%2];" \
        : "=r"(r0), "=r"(r1) : "r"(addr))

#define MMA(d, a, b0, b1) \
    asm volatile("mma.sync.aligned.m16n8k32.row.col.f32.e4m3.e4m3.f32 " \
        "{%0,%1,%2,%3}, {%4,%5,%6,%7}, {%8,%9}, {%0,%1,%2,%3};" \
        : "+f"((d)[0]), "+f"((d)[1]), "+f"((d)[2]), "+f"((d)[3]) \
        : "r"((a)[0]), "r"((a)[1]), "r"((a)[2]), "r"((a)[3]), "r"(b0), "r"(b1))

__device__ __forceinline__ uint8_t to_e4m3(float v) {
    return (uint8_t)__nv_cvt_float_to_fp8(v, __NV_SATFINITE, __NV_E4M3);
}

// ---------------- fused one-pass prep (single launch for q AND S) ----------------
template <int STRIDE, int LIMIT>
__device__ __forceinline__ void prep_body(const float* __restrict__ src, uint8_t* __restrict__ dst,
                                          int x0, float* sm, float* part, float* scl) {
    const int tid = threadIdx.x;
    for (int idx = tid; idx < 640 * 32; idx += 256) {
        int c = idx >> 5, xx = idx & 31;
        int x = x0 + xx;
        float v = (x < LIMIT) ? src[c * STRIDE + x] : 0.f;
        sm[xx * 641 + c] = v;
    }
    __syncthreads();
    {
        int g = tid >> 5, xx = tid & 31;
        float s = 0.f;
        int c0 = g * 80;
#pragma unroll 8
        for (int c = c0; c < c0 + 80; c++) {
            float v = sm[xx * 641 + c];
            s += v * v;
        }
        part[g * 32 + xx] = s;
    }
    __syncthreads();
    if (tid < 32) {
        float tot = 0.f;
#pragma unroll
        for (int g = 0; g < 8; g++) tot += part[g * 32 + tid];
        scl[tid] = 4.f / (sqrtf(tot) + EPSF);   // 4x for e4m3 range
    }
    __syncthreads();
    {
        int w = tid >> 5, lane = tid & 31;
#pragma unroll
        for (int xi = 0; xi < 4; xi++) {
            int xx = w * 4 + xi;
            int x = x0 + xx;
            if (x >= LIMIT) continue;
            float sc = scl[xx];
            uint8_t* drow = dst + (size_t)x * 640;
#pragma unroll
            for (int j = 0; j < 5; j++) {
                int c0 = (lane + 32 * j) * 4;
                const float* sp = &sm[xx * 641 + c0];
                uchar4 o;
                o.x = to_e4m3(sp[0] * sc);
                o.y = to_e4m3(sp[1] * sc);
                o.z = to_e4m3(sp[2] * sc);
                o.w = to_e4m3(sp[3] * sc);
                *(uchar4*)(drow + c0) = o;
            }
        }
    }
}

static constexpr int PREP_SMEM = 32 * 641 * 4 + (256 + 32) * 4;  // 83,200
// grid: [0,345) = S blocks (n = bid/69, xb = bid%69); [345,1395) = q blocks.

__global__ void prep_all(const float* __restrict__ q, const float* __restrict__ S) {
    extern __shared__ float smf[];
    float* part = smf + 32 * 641;
    float* scl = part + 256;
    int bid = blockIdx.x;
    if (bid < 345) {
        int n = bid / 69, xb = bid - n * 69;
        if (xb < 2) {  // zero sums: 2 xb x 5 n x 256 = 2560 >= 1875
            int ci = (xb * 5 + n) * 256 + (int)threadIdx.x;
            if (ci < 75 * 5) g_isum[ci] = 0.f;
            if (ci < 75 * 5 * 5) g_csum[ci] = 0.f;
        }
        prep_body<2205, 2205>(S + (size_t)n * 640 * 2205, g_st + (size_t)n * 2205 * 640,
                              xb * 32, smf, part, scl);
    } else {
        int r = bid - 345;
        int b = r / 14, xb = r - b * 14;
        prep_body<441, 441>(q + (size_t)b * 640 * 441, g_qt + (size_t)b * 441 * 640,
                            xb * 32, smf, part, scl);
    }
}

// ---------------- fused FP8 MMA GEMM + top-k ----------------
// grid (mt=7, n=5, b=75), 256 thr, 2 CTAs/SM. CTA tile 64 rows x 112 cols.
// A: 5 slabs [64 x 128B] SW128 resident. B: 4-slot mbarrier ring, produce-ahead 2.
// B slab = 112 rows x 128 B = 896 x 16B chunks (u==3 only for tid<128).
static constexpr int SMA_OFF = 1024;
static constexpr int SMB_OFF = SMA_OFF + 5 * 8192;            // 41984
static constexpr int MRG_OFF = SMB_OFF + 4 * 14336;           // 99328
static constexpr int SMEM_TOTAL = MRG_OFF + 64 * 2 * 3 * 4;   // 100864

__global__ __launch_bounds__(256, 2) void gemm_topk() {
    extern __shared__ char smem[];
    const uint32_t sb = smem_u32(smem);
    const uint32_t MB_FULL = sb;        // 4 x 8B
    const uint32_t MB_EMPTY = sb + 32;  // 4 x 8B
    const uint32_t smA = sb + SMA_OFF;
    const uint32_t smB = sb + SMB_OFF;
    float* mrg = (float*)(smem + MRG_OFF);

    const int tid = threadIdx.x;
    const int w = tid >> 5, lane = tid & 31;
    const int wy = w >> 1, wx = w & 1;
    const int mt = blockIdx.x, n = blockIdx.y, b = blockIdx.z;
    const int mbase = mt * 64;

    const uint8_t* Ab = g_qt + (size_t)b * 441 * 640;
    const uint8_t* Bb = g_st + (size_t)n * 2205 * 640;

    if (tid == 0) {
#pragma unroll
        for (int i = 0; i < 4; i++) {
            MBAR_INIT(MB_FULL + 8 * i, 256);
            MBAR_INIT(MB_EMPTY + 8 * i, 8);
        }
    }
    if (mbase + 63 >= 441) {
        for (int a = tid; a < 5 * 64; a += 256) {
            int slab = a >> 6, row = a & 63;
            if (mbase + row >= 441) {
                uint32_t base = slab * 8192 + row * 128;
#pragma unroll
                for (int c16 = 0; c16 < 8; c16++)
                    *(uint4*)(smem + SMA_OFF + swz(base + c16 * 16)) = make_uint4(0, 0, 0, 0);
            }
        }
    }
    __syncthreads();

    // A cp.asyncs (full K, 5 slabs of [64 x 128B])
    for (int a = tid; a < 2560; a += 256) {
        int slab = a >> 9, rem = a & 511;
        int row = rem >> 3, c16 = rem & 7;
        int x = mbase + row;
        if (x < 441) {
            uint32_t dst = smA + slab * 8192 + swz(row * 128 + c16 * 16);
            CP16(dst, __cvta_generic_to_global(Ab + (size_t)x * 640 + slab * 128 + c16 * 16));
        }
    }

    // per-thread precomputed produce bases (chunk u valid iff u<3 || tid<128)
    const uint8_t* gB[4];
    uint32_t dstoff[4];
    int rowu[4];
#pragma unroll
    for (int u = 0; u < 4; u++) {
        int ci = tid + u * 256;
        int row = ci >> 3, c16 = ci & 7;
        gB[u] = Bb + (size_t)row * 640 + c16 * 16;
        dstoff[u] = swz(row * 128 + c16 * 16);
        rowu[u] = row;
    }
    const bool has4 = (tid < 128);

    // produce B slab g into slot g%4
    auto produce = [&](int g) {
        if (g >= 100) return;
        if (g >= 4) MBAR_WAIT_RELAXED(MB_EMPTY + 8 * (g & 3), ((g >> 2) + 1) & 1);
        int T = g / 5, k = g - T * 5;
        int m0 = (T >> 2) * 441 + (T & 3) * 112;
        uint64_t goff = (uint64_t)m0 * 640 + (uint32_t)(k * 128);
        uint32_t slot = smB + (uint32_t)(g & 3) * 14336;
        if (g < 95) {
#pragma unroll
            for (int u = 0; u < 4; u++)
                if (u < 3 || has4)
                    CP16(slot + dstoff[u], __cvta_generic_to_global(gB[u] + goff));
        } else {
#pragma unroll
            for (int u = 0; u < 4; u++)
                if ((u < 3 || has4) && m0 + rowu[u] < 2205)
                    CP16(slot + dstoff[u], __cvta_generic_to_global(gB[u] + goff));
        }
        CP_MBAR_ARRIVE(MB_FULL + 8 * (g & 3));
    };

    produce(0); produce(1);   // produce-ahead 2

    // precomputed swizzled fragment offsets (slab-relative)
    uint32_t aoff[4], boff[4][3], boff2[4];
    {
        int blk = lane >> 3;
#pragma unroll
        for (int kk = 0; kk < 4; kk++) {
            {
                int row = wy * 16 + (lane & 15);
                aoff[kk] = swz(row * 128 + kk * 32 + (lane >> 4) * 16);
            }
#pragma unroll
            for (int tp = 0; tp < 3; tp++) {
                int nrow = wx * 56 + tp * 16 + (blk >> 1) * 8 + (lane & 7);
                boff[kk][tp] = swz(nrow * 128 + kk * 32 + (blk & 1) * 16);
            }
            {
                int nrow = wx * 56 + 48 + (lane & 7);
                boff2[kk] = swz(nrow * 128 + kk * 32 + ((lane >> 3) & 1) * 16);
            }
        }
    }

    float gt0 = NEGINF, gt1 = NEGINF, gt2 = NEGINF;
    int cc = 0;

    uint32_t bfr[2][14];
    auto loadB = [&](uint32_t bS, int kk, int p) {
#pragma unroll
        for (int tp = 0; tp < 3; tp++)
            LDSM_X4(bfr[p][tp * 4 + 0], bfr[p][tp * 4 + 1], bfr[p][tp * 4 + 2], bfr[p][tp * 4 + 3],
                    bS + boff[kk][tp]);
        LDSM_X2(bfr[p][12], bfr[p][13], bS + boff2[kk]);
    };

    const __half2 NEGH = __float2half2_rn(-60000.f);

    for (int s = 0; s < 5; s++) {
        // packed chunk top3: lane.x = row (wy*16 + lane>>2), lane.y = row+8
        __half2 tp0 = NEGH, tp1 = NEGH, tp2 = NEGH;

#pragma unroll
        for (int nt = 0; nt < 4; nt++) {
            float acc[7][4];
#pragma unroll
            for (int t = 0; t < 7; t++)
#pragma unroll
                for (int e = 0; e < 4; e++) acc[t][e] = 0.f;

            for (int k = 0; k < 5; k++, cc++) {
                produce(cc + 2);
                MBAR_WAIT(MB_FULL + 8 * (cc & 3), (cc >> 2) & 1);

                uint32_t aS = smA + k * 8192;
                uint32_t bS = smB + (uint32_t)(cc & 3) * 14336;

                uint32_t afr[2][4];   // double-buffered A fragments
                LDSM_X4(afr[0][0], afr[0][1], afr[0][2], afr[0][3], aS + aoff[0]);
                loadB(bS, 0, 0);
#pragma unroll
                for (int kk = 0; kk < 4; kk++) {
                    const int p = kk & 1;
                    if (kk < 3) {
                        LDSM_X4(afr[p ^ 1][0], afr[p ^ 1][1], afr[p ^ 1][2], afr[p ^ 1][3],
                                aS + aoff[kk + 1]);
                        loadB(bS, kk + 1, p ^ 1);
                    }
#pragma unroll
                    for (int tp = 0; tp < 3; tp++) {
                        MMA(acc[2 * tp],     afr[p], bfr[p][4 * tp],     bfr[p][4 * tp + 1]);
                        MMA(acc[2 * tp + 1], afr[p], bfr[p][4 * tp + 2], bfr[p][4 * tp + 3]);
                    }
                    MMA(acc[6], afr[p], bfr[p][12], bfr[p][13]);
                }
                if (lane == 0) MBAR_ARRIVE(MB_EMPTY + 8 * (cc & 3));
            }

            // ntile epilogue: packed fp16x2 top3 (pair = same col, rows r / r+8)
            int colbase = nt * 112 + wx * 56 + (lane & 3) * 2;
#pragma unroll
            for (int t = 0; t < 7; t++) {
                int c0 = colbase + t * 8;
                if (nt < 3 || c0 < 441)
                    top3h(__floats2half2_rn(acc[t][0], acc[t][2]), tp0, tp1, tp2);
                if (nt < 3 || c0 + 1 < 441)
                    top3h(__floats2half2_rn(acc[t][1], acc[t][3]), tp0, tp1, tp2);
            }
        }  // nt

        // unpack to fp32 triples, then merge across lane%4
        float tri[2][3];
        {
            float2 f0 = __half22float2(tp0);
            float2 f1 = __half22float2(tp1);
            float2 f2 = __half22float2(tp2);
            tri[0][0] = f0.x; tri[0][1] = f1.x; tri[0][2] = f2.x;
            tri[1][0] = f0.y; tri[1][1] = f1.y; tri[1][2] = f2.y;
        }
#pragma unroll
        for (int h = 0; h < 2; h++)
#pragma unroll
            for (int ofs = 1; ofs <= 2; ofs <<= 1) {
                float o0 = __shfl_xor_sync(0xFFFFFFFFu, tri[h][0], ofs);
                float o1 = __shfl_xor_sync(0xFFFFFFFFu, tri[h][1], ofs);
                float o2 = __shfl_xor_sync(0xFFFFFFFFu, tri[h][2], ofs);
                top3(o0, tri[h][0], tri[h][1], tri[h][2]);
                top3(o1, tri[h][0], tri[h][1], tri[h][2]);
                top3(o2, tri[h][0], tri[h][1], tri[h][2]);
            }
        if ((lane & 3) == 0) {
#pragma unroll
            for (int h = 0; h < 2; h++) {
                int row = wy * 16 + h * 8 + (lane >> 2);
                float* p = &mrg[(row * 2 + wx) * 3];
                p[0] = tri[h][0] * 0.0625f;   // descale here (1/16)
                p[1] = tri[h][1] * 0.0625f;
                p[2] = tri[h][2] * 0.0625f;
            }
        }
        __syncthreads();
        if (tid < 64) {
            float c0 = mrg[(tid * 2) * 3], c1 = mrg[(tid * 2) * 3 + 1], c2 = mrg[(tid * 2) * 3 + 2];
            top3(mrg[(tid * 2 + 1) * 3],     c0, c1, c2);
            top3(mrg[(tid * 2 + 1) * 3 + 1], c0, c1, c2);
            top3(mrg[(tid * 2 + 1) * 3 + 2], c0, c1, c2);
            bool valid = (mbase + tid) < 441;
            float cs = valid ? (c0 + c1 + c2) : 0.f;
#pragma unroll
            for (int o = 16; o; o >>= 1) cs += __shfl_xor_sync(0xFFFFFFFFu, cs, o);
            if (lane == 0) atomicAdd(&g_csum[(b * 5 + n) * 5 + s], cs);
            top3(c0, gt0, gt1, gt2);
            top3(c1, gt0, gt1, gt2);
            top3(c2, gt0, gt1, gt2);
        }
        __syncthreads();
    }  // chunks

    if (tid < 64) {
        bool valid = (mbase + tid) < 441;
        float gs = valid ? (gt0 + gt1 + gt2) : 0.f;
#pragma unroll
        for (int o = 16; o; o >>= 1) gs += __shfl_xor_sync(0xFFFFFFFFu, gs, o);
        if (lane == 0) atomicAdd(&g_isum[b * 5 + n], gs);
    }
}

// ---------------- finalize ----------------
__global__ void finalize_kernel(float* __restrict__ out) {
    int t = threadIdx.x;
    if (t < 75) {
        int g = t / 5, n = t % 5;
        float acc = 0.f;
        for (int a = 0; a < 5; a++) acc += logf(g_isum[(g * 5 + a) * 5 + n]);
        out[t] = expf(acc * 0.2f);
    }
    if (t < 375) {
        int g = t / 25, rem = t % 25, n = rem / 5, s = rem % 5;
        float acc = 0.f;
        for (int a = 0; a < 5; a++)
            acc += logf(fmaxf(g_csum[((g * 5 + a) * 5 + n) * 5 + s], 1e-8f));
        out[75 + t] = expf(acc * 0.2f);
    }
}

// ---------------- host ----------------
extern "C" void kernel_launch(void* const* d_in, const int* in_sizes, int n_in,
                              void* d_out, int out_size) {
    const float* q = (const float*)d_in[0];
    const float* S = (const float*)d_in[1];
    float* out = (float*)d_out;

    cudaFuncSetAttribute(prep_all, cudaFuncAttributeMaxDynamicSharedMemorySize, PREP_SMEM);
    prep_all<<<1395, 256, PREP_SMEM>>>(q, S);          // #1 (S + q prep in parallel)

    cudaFuncSetAttribute(gemm_topk, cudaFuncAttributeMaxDynamicSharedMemorySize, SMEM_TOTAL);
    gemm_topk<<<dim3(7, 5, 75), 256, SMEM_TOTAL>>>();  // #2 (profiled)

    finalize_kernel<<<1, 512>>>(out);                  // #3
}

// round 15
// speedup vs baseline: 1.0362x; 1.0166x over previous
#include <cuda_runtime.h>
#include <cuda_bf16.h>
#include <cuda_fp16.h>
#include <cuda_fp8.h>
#include <cstdint>

// q [75,640,441] f32, S [5,640,2205] f32 -> sim [15,5] ++ tks [15,5,5] (450 f32)
// FP8 e4m3: operands = 4 * normalized vectors; descale 1/16 at chunk merge.
// Top-3 tracking in packed fp16x2 (rows r / r+8 share a lane pair).

#define EPSF 1e-8f
#define NEGINF (-1e30f)

// ---------------- device scratch ----------------
__device__ __align__(16) uint8_t g_qt[75 * 441 * 640];   // e4m3, [b][x][c]
__device__ __align__(16) uint8_t g_st[5 * 2205 * 640];   // e4m3, [n][m][c]
__device__ float g_isum[75 * 5];
__device__ float g_csum[75 * 5 * 5];

// ---------------- helpers ----------------
__device__ __forceinline__ uint32_t smem_u32(const void* p) {
    uint32_t a;
    asm("{ .reg .u64 t; cvta.to.shared.u64 t, %1; cvt.u32.u64 %0, t; }" : "=r"(a) : "l"(p));
    return a;
}
__device__ __forceinline__ uint32_t swz(uint32_t x) { return x ^ ((x >> 3) & 0x70); }

__device__ __forceinline__ void top3(float v, float& t0, float& t1, float& t2) {
    float b1 = fminf(t0, v);
    t0 = fmaxf(t0, v);
    float b2 = fminf(t1, b1);
    t1 = fmaxf(t1, b1);
    t2 = fmaxf(t2, b2);
}

// packed half2 top-3 insertion (lane-wise), sorted t0>=t1>=t2
__device__ __forceinline__ void top3h(__half2 v, __half2& t0, __half2& t1, __half2& t2) {
    __half2 b1 = __hmin2(t0, v);
    t0 = __hmax2(t0, v);
    __half2 b2 = __hmin2(t1, b1);
    t1 = __hmax2(t1, b1);
    t2 = __hmax2(t2, b2);
}

#define CP16(dst, src) \
    asm volatile("cp.async.cg.shared.global [%0], [%1], 16;" :: "r"(dst), "l"(src) : "memory")
#define CP_MBAR_ARRIVE(a) \
    asm volatile("cp.async.mbarrier.arrive.noinc.shared.b64 [%0];" :: "r"(a) : "memory")
#define MBAR_INIT(a, c) \
    asm volatile("mbarrier.init.shared.b64 [%0], %1;" :: "r"(a), "r"((uint32_t)(c)) : "memory")
#define MBAR_ARRIVE(a) \
    asm volatile("mbarrier.arrive.shared.b64 _, [%0];" :: "r"(a) : "memory")
#define MBAR_WAIT(a, ph) do { \
    uint32_t _m = (a), _p = (ph), _d; \
    asm volatile("{\n\t.reg .pred p;\n\tmbarrier.try_wait.parity.acquire.cta.shared::cta.b64 p, [%1], %2;\n\tselp.b32 %0, 1, 0, p;\n\t}" \
        : "=r"(_d) : "r"(_m), "r"(_p) : "memory"); \
    if (!_d) { \
        asm volatile("{\n\t.reg .pred P1;\n\tWL_%=:\n\tmbarrier.try_wait.parity.acquire.cta.shared::cta.b64 P1, [%0], %1, 0x989680;\n\t@P1 bra.uni WD_%=;\n\tbra.uni WL_%=;\n\tWD_%=:\n\t}" \
            :: "r"(_m), "r"(_p) : "memory"); \
    } \
} while (0)

// relaxed wait: producer empty-waits only (post-wait accesses are cp.async = async proxy)
#define MBAR_WAIT_RELAXED(a, ph) do { \
    uint32_t _m = (a), _p = (ph), _d; \
    asm volatile("{\n\t.reg .pred p;\n\tmbarrier.try_wait.parity.relaxed.cta.shared::cta.b64 p, [%1], %2;\n\tselp.b32 %0, 1, 0, p;\n\t}" \
        : "=r"(_d) : "r"(_m), "r"(_p) : "memory"); \
    if (!_d) { \
        asm volatile("{\n\t.reg .pred P1;\n\tWL_%=:\n\tmbarrier.try_wait.parity.relaxed.cta.shared::cta.b64 P1, [%0], %1, 0x989680;\n\t@P1 bra.uni WD_%=;\n\tbra.uni WL_%=;\n\tWD_%=:\n\t}" \
            :: "r"(_m), "r"(_p) : "memory"); \
    } \
} while (0)

#define LDSM_X4(r0, r1, r2, r3, addr) \
    asm volatile("ldmatrix.sync.aligned.m8n8.x4.shared.b16 {%0,%1,%2,%3}, [%4];" \
        : "=r"(r0), "=r"(r1), "=r"(r2), "=r"(r3) : "r"(addr))
#define LDSM_X2(r0, r1, addr) \
    asm volatile("ldmatrix.sync.aligned.m8n8.x2.shared.b16 {%0,%1}, [%2];" \
        : "=r"(r0), "=r"(r1) : "r"(addr))

#define MMA(d, a, b0, b1) \
    asm volatile("mma.sync.aligned.m16n8k32.row.col.f32.e4m3.e4m3.f32 " \
        "{%0,%1,%2,%3}, {%4,%5,%6,%7}, {%8,%9}, {%0,%1,%2,%3};" \
        : "+f"((d)[0]), "+f"((d)[1]), "+f"((d)[2]), "+f"((d)[3]) \
        : "r"((a)[0]), "r"((a)[1]), "r"((a)[2]), "r"((a)[3]), "r"(b0), "r"(b1))

__device__ __forceinline__ uint8_t to_e4m3(float v) {
    return (uint8_t)__nv_cvt_float_to_fp8(v, __NV_SATFINITE, __NV_E4M3);
}

// ---------------- fused one-pass prep (512 threads, single launch for q AND S) ----------------
template <int STRIDE, int LIMIT>
__device__ __forceinline__ void prep_body(const float* __restrict__ src, uint8_t* __restrict__ dst,
                                          int x0, float* sm, float* part, float* scl) {
    const int tid = threadIdx.x;  // 0..511
    // load: sm[xx][c], pitch 641; 40 iters/thread
    for (int idx = tid; idx < 640 * 32; idx += 512) {
        int c = idx >> 5, xx = idx & 31;
        int x = x0 + xx;
        float v = (x < LIMIT) ? src[c * STRIDE + x] : 0.f;
        sm[xx * 641 + c] = v;
    }
    __syncthreads();
    // partial norms: 16 groups x 40 columns
    {
        int g = tid >> 5, xx = tid & 31;
        float s = 0.f;
        int c0 = g * 40;
#pragma unroll 8
        for (int c = c0; c < c0 + 40; c++) {
            float v = sm[xx * 641 + c];
            s += v * v;
        }
        part[g * 32 + xx] = s;
    }
    __syncthreads();
    if (tid < 32) {
        float tot = 0.f;
#pragma unroll
        for (int g = 0; g < 16; g++) tot += part[g * 32 + tid];
        scl[tid] = 4.f / (sqrtf(tot) + EPSF);   // 4x for e4m3 range
    }
    __syncthreads();
    // write: 16 warps x 2 rows each
    {
        int w = tid >> 5, lane = tid & 31;
#pragma unroll
        for (int xi = 0; xi < 2; xi++) {
            int xx = w * 2 + xi;
            int x = x0 + xx;
            if (x >= LIMIT) continue;
            float sc = scl[xx];
            uint8_t* drow = dst + (size_t)x * 640;
#pragma unroll
            for (int j = 0; j < 5; j++) {
                int c0 = (lane + 32 * j) * 4;
                const float* sp = &sm[xx * 641 + c0];
                uchar4 o;
                o.x = to_e4m3(sp[0] * sc);
                o.y = to_e4m3(sp[1] * sc);
                o.z = to_e4m3(sp[2] * sc);
                o.w = to_e4m3(sp[3] * sc);
                *(uchar4*)(drow + c0) = o;
            }
        }
    }
}

static constexpr int PREP_SMEM = 32 * 641 * 4 + (512 + 32) * 4;  // 84,224
// grid: [0,345) = S blocks (n = bid/69, xb = bid%69); [345,1395) = q blocks.

__global__ void prep_all(const float* __restrict__ q, const float* __restrict__ S) {
    extern __shared__ float smf[];
    float* part = smf + 32 * 641;
    float* scl = part + 512;
    int bid = blockIdx.x;
    if (bid < 345) {
        int n = bid / 69, xb = bid - n * 69;
        if (xb < 2) {  // zero sums: (xb*5+n) in 0..9, x512 covers 0..5119 >= 1875
            int ci = (xb * 5 + n) * 512 + (int)threadIdx.x;
            if (ci < 75 * 5) g_isum[ci] = 0.f;
            if (ci < 75 * 5 * 5) g_csum[ci] = 0.f;
        }
        prep_body<2205, 2205>(S + (size_t)n * 640 * 2205, g_st + (size_t)n * 2205 * 640,
                              xb * 32, smf, part, scl);
    } else {
        int r = bid - 345;
        int b = r / 14, xb = r - b * 14;
        prep_body<441, 441>(q + (size_t)b * 640 * 441, g_qt + (size_t)b * 441 * 640,
                            xb * 32, smf, part, scl);
    }
}

// ---------------- fused FP8 MMA GEMM + top-k ----------------
// grid (mt=7, n=5, b=75), 256 thr, 2 CTAs/SM. CTA tile 64 rows x 112 cols.
// A: 5 slabs [64 x 128B] SW128 resident. B: 4-slot mbarrier ring, produce-ahead 2.
// B slab = 112 rows x 128 B = 896 x 16B chunks (u==3 only for tid<128).
static constexpr int SMA_OFF = 1024;
static constexpr int SMB_OFF = SMA_OFF + 5 * 8192;            // 41984
static constexpr int MRG_OFF = SMB_OFF + 4 * 14336;           // 99328
static constexpr int SMEM_TOTAL = MRG_OFF + 64 * 2 * 3 * 4;   // 100864

__global__ __launch_bounds__(256, 2) void gemm_topk() {
    extern __shared__ char smem[];
    const uint32_t sb = smem_u32(smem);
    const uint32_t MB_FULL = sb;        // 4 x 8B
    const uint32_t MB_EMPTY = sb + 32;  // 4 x 8B
    const uint32_t smA = sb + SMA_OFF;
    const uint32_t smB = sb + SMB_OFF;
    float* mrg = (float*)(smem + MRG_OFF);

    const int tid = threadIdx.x;
    const int w = tid >> 5, lane = tid & 31;
    const int wy = w >> 1, wx = w & 1;
    const int mt = blockIdx.x, n = blockIdx.y, b = blockIdx.z;
    const int mbase = mt * 64;

    const uint8_t* Ab = g_qt + (size_t)b * 441 * 640;
    const uint8_t* Bb = g_st + (size_t)n * 2205 * 640;

    if (tid == 0) {
#pragma unroll
        for (int i = 0; i < 4; i++) {
            MBAR_INIT(MB_FULL + 8 * i, 256);
            MBAR_INIT(MB_EMPTY + 8 * i, 8);
        }
    }
    if (mbase + 63 >= 441) {
        for (int a = tid; a < 5 * 64; a += 256) {
            int slab = a >> 6, row = a & 63;
            if (mbase + row >= 441) {
                uint32_t base = slab * 8192 + row * 128;
#pragma unroll
                for (int c16 = 0; c16 < 8; c16++)
                    *(uint4*)(smem + SMA_OFF + swz(base + c16 * 16)) = make_uint4(0, 0, 0, 0);
            }
        }
    }
    __syncthreads();

    // A cp.asyncs (full K, 5 slabs of [64 x 128B])
    for (int a = tid; a < 2560; a += 256) {
        int slab = a >> 9, rem = a & 511;
        int row = rem >> 3, c16 = rem & 7;
        int x = mbase + row;
        if (x < 441) {
            uint32_t dst = smA + slab * 8192 + swz(row * 128 + c16 * 16);
            CP16(dst, __cvta_generic_to_global(Ab + (size_t)x * 640 + slab * 128 + c16 * 16));
        }
    }

    // per-thread precomputed produce bases (chunk u valid iff u<3 || tid<128)
    const uint8_t* gB[4];
    uint32_t dstoff[4];
    int rowu[4];
#pragma unroll
    for (int u = 0; u < 4; u++) {
        int ci = tid + u * 256;
        int row = ci >> 3, c16 = ci & 7;
        gB[u] = Bb + (size_t)row * 640 + c16 * 16;
        dstoff[u] = swz(row * 128 + c16 * 16);
        rowu[u] = row;
    }
    const bool has4 = (tid < 128);

    // produce B slab g into slot g%4
    auto produce = [&](int g) {
        if (g >= 100) return;
        if (g >= 4) MBAR_WAIT_RELAXED(MB_EMPTY + 8 * (g & 3), ((g >> 2) + 1) & 1);
        int T = g / 5, k = g - T * 5;
        int m0 = (T >> 2) * 441 + (T & 3) * 112;
        uint64_t goff = (uint64_t)m0 * 640 + (uint32_t)(k * 128);
        uint32_t slot = smB + (uint32_t)(g & 3) * 14336;
        if (g < 95) {
#pragma unroll
            for (int u = 0; u < 4; u++)
                if (u < 3 || has4)
                    CP16(slot + dstoff[u], __cvta_generic_to_global(gB[u] + goff));
        } else {
#pragma unroll
            for (int u = 0; u < 4; u++)
                if ((u < 3 || has4) && m0 + rowu[u] < 2205)
                    CP16(slot + dstoff[u], __cvta_generic_to_global(gB[u] + goff));
        }
        CP_MBAR_ARRIVE(MB_FULL + 8 * (g & 3));
    };

    produce(0); produce(1);   // produce-ahead 2

    // precomputed swizzled fragment offsets (slab-relative)
    uint32_t aoff[4], boff[4][3], boff2[4];
    {
        int blk = lane >> 3;
#pragma unroll
        for (int kk = 0; kk < 4; kk++) {
            {
                int row = wy * 16 + (lane & 15);
                aoff[kk] = swz(row * 128 + kk * 32 + (lane >> 4) * 16);
            }
#pragma unroll
            for (int tp = 0; tp < 3; tp++) {
                int nrow = wx * 56 + tp * 16 + (blk >> 1) * 8 + (lane & 7);
                boff[kk][tp] = swz(nrow * 128 + kk * 32 + (blk & 1) * 16);
            }
            {
                int nrow = wx * 56 + 48 + (lane & 7);
                boff2[kk] = swz(nrow * 128 + kk * 32 + ((lane >> 3) & 1) * 16);
            }
        }
    }

    float gt0 = NEGINF, gt1 = NEGINF, gt2 = NEGINF;
    int cc = 0;

    uint32_t bfr[2][14];
    auto loadB = [&](uint32_t bS, int kk, int p) {
#pragma unroll
        for (int tp = 0; tp < 3; tp++)
            LDSM_X4(bfr[p][tp * 4 + 0], bfr[p][tp * 4 + 1], bfr[p][tp * 4 + 2], bfr[p][tp * 4 + 3],
                    bS + boff[kk][tp]);
        LDSM_X2(bfr[p][12], bfr[p][13], bS + boff2[kk]);
    };

    const __half2 NEGH = __float2half2_rn(-60000.f);

    for (int s = 0; s < 5; s++) {
        // packed chunk top3: lane.x = row (wy*16 + lane>>2), lane.y = row+8
        __half2 tp0 = NEGH, tp1 = NEGH, tp2 = NEGH;

#pragma unroll
        for (int nt = 0; nt < 4; nt++) {
            float acc[7][4];
#pragma unroll
            for (int t = 0; t < 7; t++)
#pragma unroll
                for (int e = 0; e < 4; e++) acc[t][e] = 0.f;

            for (int k = 0; k < 5; k++, cc++) {
                produce(cc + 2);
                MBAR_WAIT(MB_FULL + 8 * (cc & 3), (cc >> 2) & 1);

                uint32_t aS = smA + k * 8192;
                uint32_t bS = smB + (uint32_t)(cc & 3) * 14336;

                uint32_t afr[2][4];   // double-buffered A fragments
                LDSM_X4(afr[0][0], afr[0][1], afr[0][2], afr[0][3], aS + aoff[0]);
                loadB(bS, 0, 0);
#pragma unroll
                for (int kk = 0; kk < 4; kk++) {
                    const int p = kk & 1;
                    if (kk < 3) {
                        LDSM_X4(afr[p ^ 1][0], afr[p ^ 1][1], afr[p ^ 1][2], afr[p ^ 1][3],
                                aS + aoff[kk + 1]);
                        loadB(bS, kk + 1, p ^ 1);
                    }
#pragma unroll
                    for (int tp = 0; tp < 3; tp++) {
                        MMA(acc[2 * tp],     afr[p], bfr[p][4 * tp],     bfr[p][4 * tp + 1]);
                        MMA(acc[2 * tp + 1], afr[p], bfr[p][4 * tp + 2], bfr[p][4 * tp + 3]);
                    }
                    MMA(acc[6], afr[p], bfr[p][12], bfr[p][13]);
                }
                if (lane == 0) MBAR_ARRIVE(MB_EMPTY + 8 * (cc & 3));
            }

            // ntile epilogue: packed fp16x2 top3 (pair = same col, rows r / r+8)
            int colbase = nt * 112 + wx * 56 + (lane & 3) * 2;
#pragma unroll
            for (int t = 0; t < 7; t++) {
                int c0 = colbase + t * 8;
                if (nt < 3 || c0 < 441)
                    top3h(__floats2half2_rn(acc[t][0], acc[t][2]), tp0, tp1, tp2);
                if (nt < 3 || c0 + 1 < 441)
                    top3h(__floats2half2_rn(acc[t][1], acc[t][3]), tp0, tp1, tp2);
            }
        }  // nt

        // unpack to fp32 triples, then merge across lane%4
        float tri[2][3];
        {
            float2 f0 = __half22float2(tp0);
            float2 f1 = __half22float2(tp1);
            float2 f2 = __half22float2(tp2);
            tri[0][0] = f0.x; tri[0][1] = f1.x; tri[0][2] = f2.x;
            tri[1][0] = f0.y; tri[1][1] = f1.y; tri[1][2] = f2.y;
        }
#pragma unroll
        for (int h = 0; h < 2; h++)
#pragma unroll
            for (int ofs = 1; ofs <= 2; ofs <<= 1) {
                float o0 = __shfl_xor_sync(0xFFFFFFFFu, tri[h][0], ofs);
                float o1 = __shfl_xor_sync(0xFFFFFFFFu, tri[h][1], ofs);
                float o2 = __shfl_xor_sync(0xFFFFFFFFu, tri[h][2], ofs);
                top3(o0, tri[h][0], tri[h][1], tri[h][2]);
                top3(o1, tri[h][0], tri[h][1], tri[h][2]);
                top3(o2, tri[h][0], tri[h][1], tri[h][2]);
            }
        if ((lane & 3) == 0) {
#pragma unroll
            for (int h = 0; h < 2; h++) {
                int row = wy * 16 + h * 8 + (lane >> 2);
                float* p = &mrg[(row * 2 + wx) * 3];
                p[0] = tri[h][0] * 0.0625f;   // descale here (1/16)
                p[1] = tri[h][1] * 0.0625f;
                p[2] = tri[h][2] * 0.0625f;
            }
        }
        __syncthreads();
        if (tid < 64) {
            float c0 = mrg[(tid * 2) * 3], c1 = mrg[(tid * 2) * 3 + 1], c2 = mrg[(tid * 2) * 3 + 2];
            top3(mrg[(tid * 2 + 1) * 3],     c0, c1, c2);
            top3(mrg[(tid * 2 + 1) * 3 + 1], c0, c1, c2);
            top3(mrg[(tid * 2 + 1) * 3 + 2], c0, c1, c2);
            bool valid = (mbase + tid) < 441;
            float cs = valid ? (c0 + c1 + c2) : 0.f;
#pragma unroll
            for (int o = 16; o; o >>= 1) cs += __shfl_xor_sync(0xFFFFFFFFu, cs, o);
            if (lane == 0) atomicAdd(&g_csum[(b * 5 + n) * 5 + s], cs);
            top3(c0, gt0, gt1, gt2);
            top3(c1, gt0, gt1, gt2);
            top3(c2, gt0, gt1, gt2);
        }
        __syncthreads();
    }  // chunks

    if (tid < 64) {
        bool valid = (mbase + tid) < 441;
        float gs = valid ? (gt0 + gt1 + gt2) : 0.f;
#pragma unroll
        for (int o = 16; o; o >>= 1) gs += __shfl_xor_sync(0xFFFFFFFFu, gs, o);
        if (lane == 0) atomicAdd(&g_isum[b * 5 + n], gs);
    }
}

// ---------------- finalize ----------------
__global__ void finalize_kernel(float* __restrict__ out) {
    int t = threadIdx.x;
    if (t < 75) {
        int g = t / 5, n = t % 5;
        float acc = 0.f;
        for (int a = 0; a < 5; a++) acc += logf(g_isum[(g * 5 + a) * 5 + n]);
        out[t] = expf(acc * 0.2f);
    }
    if (t < 375) {
        int g = t / 25, rem = t % 25, n = rem / 5, s = rem % 5;
        float acc = 0.f;
        for (int a = 0; a < 5; a++)
            acc += logf(fmaxf(g_csum[((g * 5 + a) * 5 + n) * 5 + s], 1e-8f));
        out[75 + t] = expf(acc * 0.2f);
    }
}

// ---------------- host ----------------
extern "C" void kernel_launch(void* const* d_in, const int* in_sizes, int n_in,
                              void* d_out, int out_size) {
    const float* q = (const float*)d_in[0];
    const float* S = (const float*)d_in[1];
    float* out = (float*)d_out;

    cudaFuncSetAttribute(prep_all, cudaFuncAttributeMaxDynamicSharedMemorySize, PREP_SMEM);
    prep_all<<<1395, 512, PREP_SMEM>>>(q, S);          // #1 (S + q prep in parallel)

    cudaFuncSetAttribute(gemm_topk, cudaFuncAttributeMaxDynamicSharedMemorySize, SMEM_TOTAL);
    gemm_topk<<<dim3(7, 5, 75), 256, SMEM_TOTAL>>>();  // #2 (profiled)

    finalize_kernel<<<1, 512>>>(out);                  // #3
}

// round 16
// speedup vs baseline: 1.0521x; 1.0154x over previous
#include <cuda_runtime.h>
#include <cuda_bf16.h>
#include <cuda_fp16.h>
#include <cuda_fp8.h>
#include <cstdint>

// q [75,640,441] f32, S [5,640,2205] f32 -> sim [15,5] ++ tks [15,5,5] (450 f32)
// FP8 e4m3: operands = 4 * normalized vectors; descale 1/16 at chunk merge.
// Top-3 tracking in packed fp16x2 (rows r / r+8 share a lane pair).

#define EPSF 1e-8f
#define NEGINF (-1e30f)

// ---------------- device scratch ----------------
__device__ __align__(16) uint8_t g_qt[75 * 441 * 640];   // e4m3, [b][x][c]
__device__ __align__(16) uint8_t g_st[5 * 2205 * 640];   // e4m3, [n][m][c]
__device__ float g_isum[75 * 5];
__device__ float g_csum[75 * 5 * 5];

// ---------------- helpers ----------------
__device__ __forceinline__ uint32_t smem_u32(const void* p) {
    uint32_t a;
    asm("{ .reg .u64 t; cvta.to.shared.u64 t, %1; cvt.u32.u64 %0, t; }" : "=r"(a) : "l"(p));
    return a;
}
__device__ __forceinline__ uint32_t swz(uint32_t x) { return x ^ ((x >> 3) & 0x70); }

__device__ __forceinline__ void top3(float v, float& t0, float& t1, float& t2) {
    float b1 = fminf(t0, v);
    t0 = fmaxf(t0, v);
    float b2 = fminf(t1, b1);
    t1 = fmaxf(t1, b1);
    t2 = fmaxf(t2, b2);
}

// packed half2 top-3 insertion (lane-wise), sorted t0>=t1>=t2
__device__ __forceinline__ void top3h(__half2 v, __half2& t0, __half2& t1, __half2& t2) {
    __half2 b1 = __hmin2(t0, v);
    t0 = __hmax2(t0, v);
    __half2 b2 = __hmin2(t1, b1);
    t1 = __hmax2(t1, b1);
    t2 = __hmax2(t2, b2);
}

#define CP16(dst, src) \
    asm volatile("cp.async.cg.shared.global [%0], [%1], 16;" :: "r"(dst), "l"(src) : "memory")
#define CP_MBAR_ARRIVE(a) \
    asm volatile("cp.async.mbarrier.arrive.noinc.shared.b64 [%0];" :: "r"(a) : "memory")
#define MBAR_INIT(a, c) \
    asm volatile("mbarrier.init.shared.b64 [%0], %1;" :: "r"(a), "r"((uint32_t)(c)) : "memory")
#define MBAR_ARRIVE(a) \
    asm volatile("mbarrier.arrive.shared.b64 _, [%0];" :: "r"(a) : "memory")
#define MBAR_WAIT(a, ph) do { \
    uint32_t _m = (a), _p = (ph), _d; \
    asm volatile("{\n\t.reg .pred p;\n\tmbarrier.try_wait.parity.acquire.cta.shared::cta.b64 p, [%1], %2;\n\tselp.b32 %0, 1, 0, p;\n\t}" \
        : "=r"(_d) : "r"(_m), "r"(_p) : "memory"); \
    if (!_d) { \
        asm volatile("{\n\t.reg .pred P1;\n\tWL_%=:\n\tmbarrier.try_wait.parity.acquire.cta.shared::cta.b64 P1, [%0], %1, 0x989680;\n\t@P1 bra.uni WD_%=;\n\tbra.uni WL_%=;\n\tWD_%=:\n\t}" \
            :: "r"(_m), "r"(_p) : "memory"); \
    } \
} while (0)

// relaxed wait: producer empty-waits only (post-wait accesses are cp.async = async proxy)
#define MBAR_WAIT_RELAXED(a, ph) do { \
    uint32_t _m = (a), _p = (ph), _d; \
    asm volatile("{\n\t.reg .pred p;\n\tmbarrier.try_wait.parity.relaxed.cta.shared::cta.b64 p, [%1], %2;\n\tselp.b32 %0, 1, 0, p;\n\t}" \
        : "=r"(_d) : "r"(_m), "r"(_p) : "memory"); \
    if (!_d) { \
        asm volatile("{\n\t.reg .pred P1;\n\tWL_%=:\n\tmbarrier.try_wait.parity.relaxed.cta.shared::cta.b64 P1, [%0], %1, 0x989680;\n\t@P1 bra.uni WD_%=;\n\tbra.uni WL_%=;\n\tWD_%=:\n\t}" \
            :: "r"(_m), "r"(_p) : "memory"); \
    } \
} while (0)

#define LDSM_X4(r0, r1, r2, r3, addr) \
    asm volatile("ldmatrix.sync.aligned.m8n8.x4.shared.b16 {%0,%1,%2,%3}, [%4];" \
        : "=r"(r0), "=r"(r1), "=r"(r2), "=r"(r3) : "r"(addr))
#define LDSM_X2(r0, r1, addr) \
    asm volatile("ldmatrix.sync.aligned.m8n8.x2.shared.b16 {%0,%1}, [%2];" \
        : "=r"(r0), "=r"(r1) : "r"(addr))

#define MMA(d, a, b0, b1) \
    asm volatile("mma.sync.aligned.m16n8k32.row.col.f32.e4m3.e4m3.f32 " \
        "{%0,%1,%2,%3}, {%4,%5,%6,%7}, {%8,%9}, {%0,%1,%2,%3};" \
        : "+f"((d)[0]), "+f"((d)[1]), "+f"((d)[2]), "+f"((d)[3]) \
        : "r"((a)[0]), "r"((a)[1]), "r"((a)[2]), "r"((a)[3]), "r"(b0), "r"(b1))

__device__ __forceinline__ uint8_t to_e4m3(float v) {
    return (uint8_t)__nv_cvt_float_to_fp8(v, __NV_SATFINITE, __NV_E4M3);
}

// ---------------- fused one-pass prep (bf16 staging, 512 thr, 4 CTAs/SM) ----------------
// Each thread owns ONE column (xx = tid&31) and 40 c-rows (c = (tid>>5) + 16k):
// norm accumulates in registers (full f32) during the load; values staged to a
// bf16 smem tile (pitch 642 -> conflict-free); write pass scales + e4m3-converts.
static constexpr int TPITCH = 642;

template <int STRIDE, int LIMIT>
__device__ __forceinline__ void prep_body(const float* __restrict__ src, uint8_t* __restrict__ dst,
                                          int x0, __nv_bfloat16* sm, float* part, float* scl) {
    const int tid = threadIdx.x;  // 0..511
    const int xx = tid & 31, g = tid >> 5;
    {
        int x = x0 + xx;
        float s = 0.f;
        if (x < LIMIT) {
            const float* col = src + x;
#pragma unroll 8
            for (int k = 0; k < 40; k++) {
                int c = g + 16 * k;
                float v = col[(size_t)c * STRIDE];
                s += v * v;
                sm[xx * TPITCH + c] = __float2bfloat16(v);
            }
        }
        part[g * 32 + xx] = s;
    }
    __syncthreads();
    if (tid < 32) {
        float tot = 0.f;
#pragma unroll
        for (int gg = 0; gg < 16; gg++) tot += part[gg * 32 + tid];
        scl[tid] = 4.f / (sqrtf(tot) + EPSF);   // 4x for e4m3 range
    }
    __syncthreads();
    // write: 16 warps x 2 rows each
    {
        int w = tid >> 5, lane = tid & 31;
#pragma unroll
        for (int xi = 0; xi < 2; xi++) {
            int row = w * 2 + xi;
            int x = x0 + row;
            if (x >= LIMIT) continue;
            float sc = scl[row];
            uint8_t* drow = dst + (size_t)x * 640;
            const __nv_bfloat16* srow = &sm[row * TPITCH];
#pragma unroll
            for (int j = 0; j < 5; j++) {
                int c0 = (lane + 32 * j) * 4;
                uchar4 o;
                o.x = to_e4m3(__bfloat162float(srow[c0 + 0]) * sc);
                o.y = to_e4m3(__bfloat162float(srow[c0 + 1]) * sc);
                o.z = to_e4m3(__bfloat162float(srow[c0 + 2]) * sc);
                o.w = to_e4m3(__bfloat162float(srow[c0 + 3]) * sc);
                *(uchar4*)(drow + c0) = o;
            }
        }
    }
}

static constexpr int PREP_SMEM = 32 * TPITCH * 2 + (512 + 32) * 4;  // 43,264
// grid: [0,345) = S blocks (n = bid/69, xb = bid%69); [345,1395) = q blocks.

__global__ void prep_all(const float* __restrict__ q, const float* __restrict__ S) {
    extern __shared__ char smc[];
    __nv_bfloat16* sm = (__nv_bfloat16*)smc;
    float* part = (float*)(smc + 32 * TPITCH * 2);
    float* scl = part + 512;
    int bid = blockIdx.x;
    if (bid < 345) {
        int n = bid / 69, xb = bid - n * 69;
        if (xb < 2) {  // zero sums: (xb*5+n) in 0..9, x512 covers 0..5119 >= 1875
            int ci = (xb * 5 + n) * 512 + (int)threadIdx.x;
            if (ci < 75 * 5) g_isum[ci] = 0.f;
            if (ci < 75 * 5 * 5) g_csum[ci] = 0.f;
        }
        prep_body<2205, 2205>(S + (size_t)n * 640 * 2205, g_st + (size_t)n * 2205 * 640,
                              xb * 32, sm, part, scl);
    } else {
        int r = bid - 345;
        int b = r / 14, xb = r - b * 14;
        prep_body<441, 441>(q + (size_t)b * 640 * 441, g_qt + (size_t)b * 441 * 640,
                            xb * 32, sm, part, scl);
    }
}

// ---------------- fused FP8 MMA GEMM + top-k ----------------
// grid (mt=7, n=5, b=75), 256 thr, 2 CTAs/SM. CTA tile 64 rows x 112 cols.
// A: 5 slabs [64 x 128B] SW128 resident. B: 4-slot mbarrier ring, produce-ahead 2.
// B slab = 112 rows x 128 B = 896 x 16B chunks (u==3 only for tid<128).
static constexpr int SMA_OFF = 1024;
static constexpr int SMB_OFF = SMA_OFF + 5 * 8192;            // 41984
static constexpr int MRG_OFF = SMB_OFF + 4 * 14336;           // 99328
static constexpr int SMEM_TOTAL = MRG_OFF + 64 * 2 * 3 * 4;   // 100864

__global__ __launch_bounds__(256, 2) void gemm_topk() {
    extern __shared__ char smem[];
    const uint32_t sb = smem_u32(smem);
    const uint32_t MB_FULL = sb;        // 4 x 8B
    const uint32_t MB_EMPTY = sb + 32;  // 4 x 8B
    const uint32_t smA = sb + SMA_OFF;
    const uint32_t smB = sb + SMB_OFF;
    float* mrg = (float*)(smem + MRG_OFF);

    const int tid = threadIdx.x;
    const int w = tid >> 5, lane = tid & 31;
    const int wy = w >> 1, wx = w & 1;
    const int mt = blockIdx.x, n = blockIdx.y, b = blockIdx.z;
    const int mbase = mt * 64;

    const uint8_t* Ab = g_qt + (size_t)b * 441 * 640;
    const uint8_t* Bb = g_st + (size_t)n * 2205 * 640;

    if (tid == 0) {
#pragma unroll
        for (int i = 0; i < 4; i++) {
            MBAR_INIT(MB_FULL + 8 * i, 256);
            MBAR_INIT(MB_EMPTY + 8 * i, 8);
        }
    }
    if (mbase + 63 >= 441) {
        for (int a = tid; a < 5 * 64; a += 256) {
            int slab = a >> 6, row = a & 63;
            if (mbase + row >= 441) {
                uint32_t base = slab * 8192 + row * 128;
#pragma unroll
                for (int c16 = 0; c16 < 8; c16++)
                    *(uint4*)(smem + SMA_OFF + swz(base + c16 * 16)) = make_uint4(0, 0, 0, 0);
            }
        }
    }
    __syncthreads();

    // A cp.asyncs (full K, 5 slabs of [64 x 128B])
    for (int a = tid; a < 2560; a += 256) {
        int slab = a >> 9, rem = a & 511;
        int row = rem >> 3, c16 = rem & 7;
        int x = mbase + row;
        if (x < 441) {
            uint32_t dst = smA + slab * 8192 + swz(row * 128 + c16 * 16);
            CP16(dst, __cvta_generic_to_global(Ab + (size_t)x * 640 + slab * 128 + c16 * 16));
        }
    }

    // per-thread precomputed produce bases (chunk u valid iff u<3 || tid<128)
    const uint8_t* gB[4];
    uint32_t dstoff[4];
    int rowu[4];
#pragma unroll
    for (int u = 0; u < 4; u++) {
        int ci = tid + u * 256;
        int row = ci >> 3, c16 = ci & 7;
        gB[u] = Bb + (size_t)row * 640 + c16 * 16;
        dstoff[u] = swz(row * 128 + c16 * 16);
        rowu[u] = row;
    }
    const bool has4 = (tid < 128);

    // produce B slab g into slot g%4
    auto produce = [&](int g) {
        if (g >= 100) return;
        if (g >= 4) MBAR_WAIT_RELAXED(MB_EMPTY + 8 * (g & 3), ((g >> 2) + 1) & 1);
        int T = g / 5, k = g - T * 5;
        int m0 = (T >> 2) * 441 + (T & 3) * 112;
        uint64_t goff = (uint64_t)m0 * 640 + (uint32_t)(k * 128);
        uint32_t slot = smB + (uint32_t)(g & 3) * 14336;
        if (g < 95) {
#pragma unroll
            for (int u = 0; u < 4; u++)
                if (u < 3 || has4)
                    CP16(slot + dstoff[u], __cvta_generic_to_global(gB[u] + goff));
        } else {
#pragma unroll
            for (int u = 0; u < 4; u++)
                if ((u < 3 || has4) && m0 + rowu[u] < 2205)
                    CP16(slot + dstoff[u], __cvta_generic_to_global(gB[u] + goff));
        }
        CP_MBAR_ARRIVE(MB_FULL + 8 * (g & 3));
    };

    produce(0); produce(1);   // produce-ahead 2

    // precomputed swizzled fragment offsets (slab-relative)
    uint32_t aoff[4], boff[4][3], boff2[4];
    {
        int blk = lane >> 3;
#pragma unroll
        for (int kk = 0; kk < 4; kk++) {
            {
                int row = wy * 16 + (lane & 15);
                aoff[kk] = swz(row * 128 + kk * 32 + (lane >> 4) * 16);
            }
#pragma unroll
            for (int tp = 0; tp < 3; tp++) {
                int nrow = wx * 56 + tp * 16 + (blk >> 1) * 8 + (lane & 7);
                boff[kk][tp] = swz(nrow * 128 + kk * 32 + (blk & 1) * 16);
            }
            {
                int nrow = wx * 56 + 48 + (lane & 7);
                boff2[kk] = swz(nrow * 128 + kk * 32 + ((lane >> 3) & 1) * 16);
            }
        }
    }

    float gt0 = NEGINF, gt1 = NEGINF, gt2 = NEGINF;
    int cc = 0;

    uint32_t bfr[2][14];
    auto loadB = [&](uint32_t bS, int kk, int p) {
#pragma unroll
        for (int tp = 0; tp < 3; tp++)
            LDSM_X4(bfr[p][tp * 4 + 0], bfr[p][tp * 4 + 1], bfr[p][tp * 4 + 2], bfr[p][tp * 4 + 3],
                    bS + boff[kk][tp]);
        LDSM_X2(bfr[p][12], bfr[p][13], bS + boff2[kk]);
    };

    const __half2 NEGH = __float2half2_rn(-60000.f);

    for (int s = 0; s < 5; s++) {
        // packed chunk top3: lane.x = row (wy*16 + lane>>2), lane.y = row+8
        __half2 tp0 = NEGH, tp1 = NEGH, tp2 = NEGH;

#pragma unroll
        for (int nt = 0; nt < 4; nt++) {
            float acc[7][4];
#pragma unroll
            for (int t = 0; t < 7; t++)
#pragma unroll
                for (int e = 0; e < 4; e++) acc[t][e] = 0.f;

            for (int k = 0; k < 5; k++, cc++) {
                produce(cc + 2);
                MBAR_WAIT(MB_FULL + 8 * (cc & 3), (cc >> 2) & 1);

                uint32_t aS = smA + k * 8192;
                uint32_t bS = smB + (uint32_t)(cc & 3) * 14336;

                uint32_t afr[2][4];   // double-buffered A fragments
                LDSM_X4(afr[0][0], afr[0][1], afr[0][2], afr[0][3], aS + aoff[0]);
                loadB(bS, 0, 0);
#pragma unroll
                for (int kk = 0; kk < 4; kk++) {
                    const int p = kk & 1;
                    if (kk < 3) {
                        LDSM_X4(afr[p ^ 1][0], afr[p ^ 1][1], afr[p ^ 1][2], afr[p ^ 1][3],
                                aS + aoff[kk + 1]);
                        loadB(bS, kk + 1, p ^ 1);
                    }
#pragma unroll
                    for (int tp = 0; tp < 3; tp++) {
                        MMA(acc[2 * tp],     afr[p], bfr[p][4 * tp],     bfr[p][4 * tp + 1]);
                        MMA(acc[2 * tp + 1], afr[p], bfr[p][4 * tp + 2], bfr[p][4 * tp + 3]);
                    }
                    MMA(acc[6], afr[p], bfr[p][12], bfr[p][13]);
                }
                if (lane == 0) MBAR_ARRIVE(MB_EMPTY + 8 * (cc & 3));
            }

            // ntile epilogue: packed fp16x2 top3 (pair = same col, rows r / r+8)
            int colbase = nt * 112 + wx * 56 + (lane & 3) * 2;
#pragma unroll
            for (int t = 0; t < 7; t++) {
                int c0 = colbase + t * 8;
                if (nt < 3 || c0 < 441)
                    top3h(__floats2half2_rn(acc[t][0], acc[t][2]), tp0, tp1, tp2);
                if (nt < 3 || c0 + 1 < 441)
                    top3h(__floats2half2_rn(acc[t][1], acc[t][3]), tp0, tp1, tp2);
            }
        }  // nt

        // unpack to fp32 triples, then merge across lane%4
        float tri[2][3];
        {
            float2 f0 = __half22float2(tp0);
            float2 f1 = __half22float2(tp1);
            float2 f2 = __half22float2(tp2);
            tri[0][0] = f0.x; tri[0][1] = f1.x; tri[0][2] = f2.x;
            tri[1][0] = f0.y; tri[1][1] = f1.y; tri[1][2] = f2.y;
        }
#pragma unroll
        for (int h = 0; h < 2; h++)
#pragma unroll
            for (int ofs = 1; ofs <= 2; ofs <<= 1) {
                float o0 = __shfl_xor_sync(0xFFFFFFFFu, tri[h][0], ofs);
                float o1 = __shfl_xor_sync(0xFFFFFFFFu, tri[h][1], ofs);
                float o2 = __shfl_xor_sync(0xFFFFFFFFu, tri[h][2], ofs);
                top3(o0, tri[h][0], tri[h][1], tri[h][2]);
                top3(o1, tri[h][0], tri[h][1], tri[h][2]);
                top3(o2, tri[h][0], tri[h][1], tri[h][2]);
            }
        if ((lane & 3) == 0) {
#pragma unroll
            for (int h = 0; h < 2; h++) {
                int row = wy * 16 + h * 8 + (lane >> 2);
                float* p = &mrg[(row * 2 + wx) * 3];
                p[0] = tri[h][0] * 0.0625f;   // descale here (1/16)
                p[1] = tri[h][1] * 0.0625f;
                p[2] = tri[h][2] * 0.0625f;
            }
        }
        __syncthreads();
        if (tid < 64) {
            float c0 = mrg[(tid * 2) * 3], c1 = mrg[(tid * 2) * 3 + 1], c2 = mrg[(tid * 2) * 3 + 2];
            top3(mrg[(tid * 2 + 1) * 3],     c0, c1, c2);
            top3(mrg[(tid * 2 + 1) * 3 + 1], c0, c1, c2);
            top3(mrg[(tid * 2 + 1) * 3 + 2], c0, c1, c2);
            bool valid = (mbase + tid) < 441;
            float cs = valid ? (c0 + c1 + c2) : 0.f;
#pragma unroll
            for (int o = 16; o; o >>= 1) cs += __shfl_xor_sync(0xFFFFFFFFu, cs, o);
            if (lane == 0) atomicAdd(&g_csum[(b * 5 + n) * 5 + s], cs);
            top3(c0, gt0, gt1, gt2);
            top3(c1, gt0, gt1, gt2);
            top3(c2, gt0, gt1, gt2);
        }
        __syncthreads();
    }  // chunks

    if (tid < 64) {
        bool valid = (mbase + tid) < 441;
        float gs = valid ? (gt0 + gt1 + gt2) : 0.f;
#pragma unroll
        for (int o = 16; o; o >>= 1) gs += __shfl_xor_sync(0xFFFFFFFFu, gs, o);
        if (lane == 0) atomicAdd(&g_isum[b * 5 + n], gs);
    }
}

// ---------------- finalize ----------------
__global__ void finalize_kernel(float* __restrict__ out) {
    int t = threadIdx.x;
    if (t < 75) {
        int g = t / 5, n = t % 5;
        float acc = 0.f;
        for (int a = 0; a < 5; a++) acc += logf(g_isum[(g * 5 + a) * 5 + n]);
        out[t] = expf(acc * 0.2f);
    }
    if (t < 375) {
        int g = t / 25, rem = t % 25, n = rem / 5, s = rem % 5;
        float acc = 0.f;
        for (int a = 0; a < 5; a++)
            acc += logf(fmaxf(g_csum[((g * 5 + a) * 5 + n) * 5 + s], 1e-8f));
        out[75 + t] = expf(acc * 0.2f);
    }
}

// ---------------- host ----------------
extern "C" void kernel_launch(void* const* d_in, const int* in_sizes, int n_in,
                              void* d_out, int out_size) {
    const float* q = (const float*)d_in[0];
    const float* S = (const float*)d_in[1];
    float* out = (float*)d_out;

    cudaFuncSetAttribute(prep_all, cudaFuncAttributeMaxDynamicSharedMemorySize, PREP_SMEM);
    prep_all<<<1395, 512, PREP_SMEM>>>(q, S);          // #1 (S + q prep in parallel)

    cudaFuncSetAttribute(gemm_topk, cudaFuncAttributeMaxDynamicSharedMemorySize, SMEM_TOTAL);
    gemm_topk<<<dim3(7, 5, 75), 256, SMEM_TOTAL>>>();  // #2 (profiled)

    finalize_kernel<<<1, 512>>>(out);                  // #3
}

// round 17
// speedup vs baseline: 1.1725x; 1.1144x over previous
#include <cuda_runtime.h>
#include <cuda_bf16.h>
#include <cuda_fp16.h>
#include <cuda_fp8.h>
#include <cstdint>

// q [75,640,441] f32, S [5,640,2205] f32 -> sim [15,5] ++ tks [15,5,5] (450 f32)
// FP8 e4m3: operands = 4 * normalized vectors; descale 1/16 at chunk merge.
// GEMM: 4 fat warps (2wy x 2wx, warp tile 32x56) to halve LDSM redundancy.

#define EPSF 1e-8f
#define NEGINF (-1e30f)

// ---------------- device scratch ----------------
__device__ __align__(16) uint8_t g_qt[75 * 441 * 640];   // e4m3, [b][x][c]
__device__ __align__(16) uint8_t g_st[5 * 2205 * 640];   // e4m3, [n][m][c]
__device__ float g_isum[75 * 5];
__device__ float g_csum[75 * 5 * 5];

// ---------------- helpers ----------------
__device__ __forceinline__ uint32_t smem_u32(const void* p) {
    uint32_t a;
    asm("{ .reg .u64 t; cvta.to.shared.u64 t, %1; cvt.u32.u64 %0, t; }" : "=r"(a) : "l"(p));
    return a;
}
__device__ __forceinline__ uint32_t swz(uint32_t x) { return x ^ ((x >> 3) & 0x70); }

__device__ __forceinline__ void top3(float v, float& t0, float& t1, float& t2) {
    float b1 = fminf(t0, v);
    t0 = fmaxf(t0, v);
    float b2 = fminf(t1, b1);
    t1 = fmaxf(t1, b1);
    t2 = fmaxf(t2, b2);
}

__device__ __forceinline__ void top3h(__half2 v, __half2& t0, __half2& t1, __half2& t2) {
    __half2 b1 = __hmin2(t0, v);
    t0 = __hmax2(t0, v);
    __half2 b2 = __hmin2(t1, b1);
    t1 = __hmax2(t1, b1);
    t2 = __hmax2(t2, b2);
}

#define CP16(dst, src) \
    asm volatile("cp.async.cg.shared.global [%0], [%1], 16;" :: "r"(dst), "l"(src) : "memory")
#define CP_MBAR_ARRIVE(a) \
    asm volatile("cp.async.mbarrier.arrive.noinc.shared.b64 [%0];" :: "r"(a) : "memory")
#define MBAR_INIT(a, c) \
    asm volatile("mbarrier.init.shared.b64 [%0], %1;" :: "r"(a), "r"((uint32_t)(c)) : "memory")
#define MBAR_ARRIVE(a) \
    asm volatile("mbarrier.arrive.shared.b64 _, [%0];" :: "r"(a) : "memory")
#define MBAR_WAIT(a, ph) do { \
    uint32_t _m = (a), _p = (ph), _d; \
    asm volatile("{\n\t.reg .pred p;\n\tmbarrier.try_wait.parity.acquire.cta.shared::cta.b64 p, [%1], %2;\n\tselp.b32 %0, 1, 0, p;\n\t}" \
        : "=r"(_d) : "r"(_m), "r"(_p) : "memory"); \
    if (!_d) { \
        asm volatile("{\n\t.reg .pred P1;\n\tWL_%=:\n\tmbarrier.try_wait.parity.acquire.cta.shared::cta.b64 P1, [%0], %1, 0x989680;\n\t@P1 bra.uni WD_%=;\n\tbra.uni WL_%=;\n\tWD_%=:\n\t}" \
            :: "r"(_m), "r"(_p) : "memory"); \
    } \
} while (0)

#define MBAR_WAIT_RELAXED(a, ph) do { \
    uint32_t _m = (a), _p = (ph), _d; \
    asm volatile("{\n\t.reg .pred p;\n\tmbarrier.try_wait.parity.relaxed.cta.shared::cta.b64 p, [%1], %2;\n\tselp.b32 %0, 1, 0, p;\n\t}" \
        : "=r"(_d) : "r"(_m), "r"(_p) : "memory"); \
    if (!_d) { \
        asm volatile("{\n\t.reg .pred P1;\n\tWL_%=:\n\tmbarrier.try_wait.parity.relaxed.cta.shared::cta.b64 P1, [%0], %1, 0x989680;\n\t@P1 bra.uni WD_%=;\n\tbra.uni WL_%=;\n\tWD_%=:\n\t}" \
            :: "r"(_m), "r"(_p) : "memory"); \
    } \
} while (0)

#define LDSM_X4(r0, r1, r2, r3, addr) \
    asm volatile("ldmatrix.sync.aligned.m8n8.x4.shared.b16 {%0,%1,%2,%3}, [%4];" \
        : "=r"(r0), "=r"(r1), "=r"(r2), "=r"(r3) : "r"(addr))
#define LDSM_X2(r0, r1, addr) \
    asm volatile("ldmatrix.sync.aligned.m8n8.x2.shared.b16 {%0,%1}, [%2];" \
        : "=r"(r0), "=r"(r1) : "r"(addr))

#define MMA(d, a, b0, b1) \
    asm volatile("mma.sync.aligned.m16n8k32.row.col.f32.e4m3.e4m3.f32 " \
        "{%0,%1,%2,%3}, {%4,%5,%6,%7}, {%8,%9}, {%0,%1,%2,%3};" \
        : "+f"((d)[0]), "+f"((d)[1]), "+f"((d)[2]), "+f"((d)[3]) \
        : "r"((a)[0]), "r"((a)[1]), "r"((a)[2]), "r"((a)[3]), "r"(b0), "r"(b1))

__device__ __forceinline__ uint8_t to_e4m3(float v) {
    return (uint8_t)__nv_cvt_float_to_fp8(v, __NV_SATFINITE, __NV_E4M3);
}

// ---------------- fused one-pass prep (bf16 staging, 512 thr, 4 CTAs/SM) ----------------
static constexpr int TPITCH = 642;

template <int STRIDE, int LIMIT>
__device__ __forceinline__ void prep_body(const float* __restrict__ src, uint8_t* __restrict__ dst,
                                          int x0, __nv_bfloat16* sm, float* part, float* scl) {
    const int tid = threadIdx.x;  // 0..511
    const int xx = tid & 31, g = tid >> 5;
    {
        int x = x0 + xx;
        float s = 0.f;
        if (x < LIMIT) {
            const float* col = src + x;
#pragma unroll 8
            for (int k = 0; k < 40; k++) {
                int c = g + 16 * k;
                float v = col[(size_t)c * STRIDE];
                s += v * v;
                sm[xx * TPITCH + c] = __float2bfloat16(v);
            }
        }
        part[g * 32 + xx] = s;
    }
    __syncthreads();
    if (tid < 32) {
        float tot = 0.f;
#pragma unroll
        for (int gg = 0; gg < 16; gg++) tot += part[gg * 32 + tid];
        scl[tid] = 4.f / (sqrtf(tot) + EPSF);
    }
    __syncthreads();
    {
        int w = tid >> 5, lane = tid & 31;
#pragma unroll
        for (int xi = 0; xi < 2; xi++) {
            int row = w * 2 + xi;
            int x = x0 + row;
            if (x >= LIMIT) continue;
            float sc = scl[row];
            uint8_t* drow = dst + (size_t)x * 640;
            const __nv_bfloat16* srow = &sm[row * TPITCH];
#pragma unroll
            for (int j = 0; j < 5; j++) {
                int c0 = (lane + 32 * j) * 4;
                uchar4 o;
                o.x = to_e4m3(__bfloat162float(srow[c0 + 0]) * sc);
                o.y = to_e4m3(__bfloat162float(srow[c0 + 1]) * sc);
                o.z = to_e4m3(__bfloat162float(srow[c0 + 2]) * sc);
                o.w = to_e4m3(__bfloat162float(srow[c0 + 3]) * sc);
                *(uchar4*)(drow + c0) = o;
            }
        }
    }
}

static constexpr int PREP_SMEM = 32 * TPITCH * 2 + (512 + 32) * 4;  // 43,264

__global__ void prep_all(const float* __restrict__ q, const float* __restrict__ S) {
    extern __shared__ char smc[];
    __nv_bfloat16* sm = (__nv_bfloat16*)smc;
    float* part = (float*)(smc + 32 * TPITCH * 2);
    float* scl = part + 512;
    int bid = blockIdx.x;
    if (bid < 345) {
        int n = bid / 69, xb = bid - n * 69;
        if (xb < 2) {
            int ci = (xb * 5 + n) * 512 + (int)threadIdx.x;
            if (ci < 75 * 5) g_isum[ci] = 0.f;
            if (ci < 75 * 5 * 5) g_csum[ci] = 0.f;
        }
        prep_body<2205, 2205>(S + (size_t)n * 640 * 2205, g_st + (size_t)n * 2205 * 640,
                              xb * 32, sm, part, scl);
    } else {
        int r = bid - 345;
        int b = r / 14, xb = r - b * 14;
        prep_body<441, 441>(q + (size_t)b * 640 * 441, g_qt + (size_t)b * 441 * 640,
                            xb * 32, sm, part, scl);
    }
}

// ---------------- fused FP8 MMA GEMM + top-k (4 fat warps) ----------------
// grid (mt=7, n=5, b=75), 128 thr, 2 CTAs/SM. CTA tile 64 rows x 112 cols.
// Warps: wy=w>>1 (2 groups of 32 rows), wx=w&1 (2 groups of 56 cols).
// Warp tile 32x56: acc[2][7][4]. LDSM redundancy A x2, B x2 (was B x4).
// A: 5 slabs [64 x 128B] SW128 resident. B: 4-slot mbarrier ring, produce-ahead 2.
// B slab = 896 x 16B chunks = exactly 7 per thread.
static constexpr int SMA_OFF = 1024;
static constexpr int SMB_OFF = SMA_OFF + 5 * 8192;            // 41984
static constexpr int MRG_OFF = SMB_OFF + 4 * 14336;           // 99328
static constexpr int SMEM_TOTAL = MRG_OFF + 64 * 2 * 3 * 4;   // 100864

__global__ __launch_bounds__(128, 2) void gemm_topk() {
    extern __shared__ char smem[];
    const uint32_t sb = smem_u32(smem);
    const uint32_t MB_FULL = sb;        // 4 x 8B
    const uint32_t MB_EMPTY = sb + 32;  // 4 x 8B
    const uint32_t smA = sb + SMA_OFF;
    const uint32_t smB = sb + SMB_OFF;
    float* mrg = (float*)(smem + MRG_OFF);

    const int tid = threadIdx.x;
    const int w = tid >> 5, lane = tid & 31;
    const int wy = w >> 1, wx = w & 1;
    const int mt = blockIdx.x, n = blockIdx.y, b = blockIdx.z;
    const int mbase = mt * 64;

    const uint8_t* Ab = g_qt + (size_t)b * 441 * 640;
    const uint8_t* Bb = g_st + (size_t)n * 2205 * 640;

    if (tid == 0) {
#pragma unroll
        for (int i = 0; i < 4; i++) {
            MBAR_INIT(MB_FULL + 8 * i, 128);   // per-thread cp.async arrivals
            MBAR_INIT(MB_EMPTY + 8 * i, 4);    // per-warp arrivals
        }
    }
    if (mbase + 63 >= 441) {
        for (int a = tid; a < 5 * 64; a += 128) {
            int slab = a >> 6, row = a & 63;
            if (mbase + row >= 441) {
                uint32_t base = slab * 8192 + row * 128;
#pragma unroll
                for (int c16 = 0; c16 < 8; c16++)
                    *(uint4*)(smem + SMA_OFF + swz(base + c16 * 16)) = make_uint4(0, 0, 0, 0);
            }
        }
    }
    __syncthreads();

    // A cp.asyncs (full K, 5 slabs of [64 x 128B]), 20 per thread
    for (int a = tid; a < 2560; a += 128) {
        int slab = a >> 9, rem = a & 511;
        int row = rem >> 3, c16 = rem & 7;
        int x = mbase + row;
        if (x < 441) {
            uint32_t dst = smA + slab * 8192 + swz(row * 128 + c16 * 16);
            CP16(dst, __cvta_generic_to_global(Ab + (size_t)x * 640 + slab * 128 + c16 * 16));
        }
    }

    // per-thread precomputed produce bases: exactly 7 chunks per thread (896 = 7*128)
    const uint8_t* gB[7];
    uint32_t dstoff[7];
    int rowu[7];
#pragma unroll
    for (int u = 0; u < 7; u++) {
        int ci = tid + u * 128;
        int row = ci >> 3, c16 = ci & 7;
        gB[u] = Bb + (size_t)row * 640 + c16 * 16;
        dstoff[u] = swz(row * 128 + c16 * 16);
        rowu[u] = row;
    }

    // produce B slab g into slot g%4
    auto produce = [&](int g) {
        if (g >= 100) return;
        if (g >= 4) MBAR_WAIT_RELAXED(MB_EMPTY + 8 * (g & 3), ((g >> 2) + 1) & 1);
        int T = g / 5, k = g - T * 5;
        int m0 = (T >> 2) * 441 + (T & 3) * 112;
        uint64_t goff = (uint64_t)m0 * 640 + (uint32_t)(k * 128);
        uint32_t slot = smB + (uint32_t)(g & 3) * 14336;
        if (g < 95) {
#pragma unroll
            for (int u = 0; u < 7; u++)
                CP16(slot + dstoff[u], __cvta_generic_to_global(gB[u] + goff));
        } else {
#pragma unroll
            for (int u = 0; u < 7; u++)
                if (m0 + rowu[u] < 2205)
                    CP16(slot + dstoff[u], __cvta_generic_to_global(gB[u] + goff));
        }
        CP_MBAR_ARRIVE(MB_FULL + 8 * (g & 3));
    };

    produce(0); produce(1);   // produce-ahead 2

    // precomputed swizzled fragment offsets (slab-relative)
    uint32_t aoff[2][4], boff[4][3], boff2[4];
    {
        int blk = lane >> 3;
#pragma unroll
        for (int kk = 0; kk < 4; kk++) {
#pragma unroll
            for (int i = 0; i < 2; i++) {
                int row = wy * 32 + i * 16 + (lane & 15);
                aoff[i][kk] = swz(row * 128 + kk * 32 + (lane >> 4) * 16);
            }
#pragma unroll
            for (int tp = 0; tp < 3; tp++) {
                int nrow = wx * 56 + tp * 16 + (blk >> 1) * 8 + (lane & 7);
                boff[kk][tp] = swz(nrow * 128 + kk * 32 + (blk & 1) * 16);
            }
            {
                int nrow = wx * 56 + 48 + (lane & 7);
                boff2[kk] = swz(nrow * 128 + kk * 32 + ((lane >> 3) & 1) * 16);
            }
        }
    }

    float gt0 = NEGINF, gt1 = NEGINF, gt2 = NEGINF;
    int cc = 0;

    uint32_t bfr[2][14];
    auto loadB = [&](uint32_t bS, int kk, int p) {
#pragma unroll
        for (int tp = 0; tp < 3; tp++)
            LDSM_X4(bfr[p][tp * 4 + 0], bfr[p][tp * 4 + 1], bfr[p][tp * 4 + 2], bfr[p][tp * 4 + 3],
                    bS + boff[kk][tp]);
        LDSM_X2(bfr[p][12], bfr[p][13], bS + boff2[kk]);
    };

    const __half2 NEGH = __float2half2_rn(-60000.f);

    for (int s = 0; s < 5; s++) {
        // packed chunk top3 per i-block: lane.x = row r, lane.y = row r+8
        __half2 tpk[2][3];
#pragma unroll
        for (int i = 0; i < 2; i++) { tpk[i][0] = NEGH; tpk[i][1] = NEGH; tpk[i][2] = NEGH; }

#pragma unroll
        for (int nt = 0; nt < 4; nt++) {
            float acc[2][7][4];
#pragma unroll
            for (int i = 0; i < 2; i++)
#pragma unroll
                for (int t = 0; t < 7; t++)
#pragma unroll
                    for (int e = 0; e < 4; e++) acc[i][t][e] = 0.f;

            for (int k = 0; k < 5; k++, cc++) {
                produce(cc + 2);
                MBAR_WAIT(MB_FULL + 8 * (cc & 3), (cc >> 2) & 1);

                uint32_t aS = smA + k * 8192;
                uint32_t bS = smB + (uint32_t)(cc & 3) * 14336;

                uint32_t afr[2][2][4];   // [buf][i]
#pragma unroll
                for (int i = 0; i < 2; i++)
                    LDSM_X4(afr[0][i][0], afr[0][i][1], afr[0][i][2], afr[0][i][3], aS + aoff[i][0]);
                loadB(bS, 0, 0);
#pragma unroll
                for (int kk = 0; kk < 4; kk++) {
                    const int p = kk & 1;
                    if (kk < 3) {
#pragma unroll
                        for (int i = 0; i < 2; i++)
                            LDSM_X4(afr[p ^ 1][i][0], afr[p ^ 1][i][1], afr[p ^ 1][i][2], afr[p ^ 1][i][3],
                                    aS + aoff[i][kk + 1]);
                        loadB(bS, kk + 1, p ^ 1);
                    }
#pragma unroll
                    for (int tp = 0; tp < 3; tp++)
#pragma unroll
                        for (int i = 0; i < 2; i++) {
                            MMA(acc[i][2 * tp],     afr[p][i], bfr[p][4 * tp],     bfr[p][4 * tp + 1]);
                            MMA(acc[i][2 * tp + 1], afr[p][i], bfr[p][4 * tp + 2], bfr[p][4 * tp + 3]);
                        }
#pragma unroll
                    for (int i = 0; i < 2; i++)
                        MMA(acc[i][6], afr[p][i], bfr[p][12], bfr[p][13]);
                }
                if (lane == 0) MBAR_ARRIVE(MB_EMPTY + 8 * (cc & 3));
            }

            // ntile epilogue: packed fp16x2 top3 per i-block
            int colbase = nt * 112 + wx * 56 + (lane & 3) * 2;
#pragma unroll
            for (int t = 0; t < 7; t++) {
                int c0 = colbase + t * 8;
                bool v0 = (nt < 3 || c0 < 441);
                bool v1 = (nt < 3 || c0 + 1 < 441);
#pragma unroll
                for (int i = 0; i < 2; i++) {
                    if (v0) top3h(__floats2half2_rn(acc[i][t][0], acc[i][t][2]),
                                  tpk[i][0], tpk[i][1], tpk[i][2]);
                    if (v1) top3h(__floats2half2_rn(acc[i][t][1], acc[i][t][3]),
                                  tpk[i][0], tpk[i][1], tpk[i][2]);
                }
            }
        }  // nt

        // unpack + merge across lane%4, write mrg
#pragma unroll
        for (int i = 0; i < 2; i++) {
            float tri[2][3];
            float2 f0 = __half22float2(tpk[i][0]);
            float2 f1 = __half22float2(tpk[i][1]);
            float2 f2 = __half22float2(tpk[i][2]);
            tri[0][0] = f0.x; tri[0][1] = f1.x; tri[0][2] = f2.x;
            tri[1][0] = f0.y; tri[1][1] = f1.y; tri[1][2] = f2.y;
#pragma unroll
            for (int h = 0; h < 2; h++)
#pragma unroll
                for (int ofs = 1; ofs <= 2; ofs <<= 1) {
                    float o0 = __shfl_xor_sync(0xFFFFFFFFu, tri[h][0], ofs);
                    float o1 = __shfl_xor_sync(0xFFFFFFFFu, tri[h][1], ofs);
                    float o2 = __shfl_xor_sync(0xFFFFFFFFu, tri[h][2], ofs);
                    top3(o0, tri[h][0], tri[h][1], tri[h][2]);
                    top3(o1, tri[h][0], tri[h][1], tri[h][2]);
                    top3(o2, tri[h][0], tri[h][1], tri[h][2]);
                }
            if ((lane & 3) == 0) {
#pragma unroll
                for (int h = 0; h < 2; h++) {
                    int row = wy * 32 + i * 16 + h * 8 + (lane >> 2);
                    float* p = &mrg[(row * 2 + wx) * 3];
                    p[0] = tri[h][0] * 0.0625f;
                    p[1] = tri[h][1] * 0.0625f;
                    p[2] = tri[h][2] * 0.0625f;
                }
            }
            tpk[i][0] = NEGH; tpk[i][1] = NEGH; tpk[i][2] = NEGH;
        }
        __syncthreads();
        if (tid < 64) {
            float c0 = mrg[(tid * 2) * 3], c1 = mrg[(tid * 2) * 3 + 1], c2 = mrg[(tid * 2) * 3 + 2];
            top3(mrg[(tid * 2 + 1) * 3],     c0, c1, c2);
            top3(mrg[(tid * 2 + 1) * 3 + 1], c0, c1, c2);
            top3(mrg[(tid * 2 + 1) * 3 + 2], c0, c1, c2);
            bool valid = (mbase + tid) < 441;
            float cs = valid ? (c0 + c1 + c2) : 0.f;
#pragma unroll
            for (int o = 16; o; o >>= 1) cs += __shfl_xor_sync(0xFFFFFFFFu, cs, o);
            if (lane == 0) atomicAdd(&g_csum[(b * 5 + n) * 5 + s], cs);
            top3(c0, gt0, gt1, gt2);
            top3(c1, gt0, gt1, gt2);
            top3(c2, gt0, gt1, gt2);
        }
        __syncthreads();
    }  // chunks

    if (tid < 64) {
        bool valid = (mbase + tid) < 441;
        float gs = valid ? (gt0 + gt1 + gt2) : 0.f;
#pragma unroll
        for (int o = 16; o; o >>= 1) gs += __shfl_xor_sync(0xFFFFFFFFu, gs, o);
        if (lane == 0) atomicAdd(&g_isum[b * 5 + n], gs);
    }
}

// ---------------- finalize ----------------
__global__ void finalize_kernel(float* __restrict__ out) {
    int t = threadIdx.x;
    if (t < 75) {
        int g = t / 5, n = t % 5;
        float acc = 0.f;
        for (int a = 0; a < 5; a++) acc += logf(g_isum[(g * 5 + a) * 5 + n]);
        out[t] = expf(acc * 0.2f);
    }
    if (t < 375) {
        int g = t / 25, rem = t % 25, n = rem / 5, s = rem % 5;
        float acc = 0.f;
        for (int a = 0; a < 5; a++)
            acc += logf(fmaxf(g_csum[((g * 5 + a) * 5 + n) * 5 + s], 1e-8f));
        out[75 + t] = expf(acc * 0.2f);
    }
}

// ---------------- host ----------------
extern "C" void kernel_launch(void* const* d_in, const int* in_sizes, int n_in,
                              void* d_out, int out_size) {
    const float* q = (const float*)d_in[0];
    const float* S = (const float*)d_in[1];
    float* out = (float*)d_out;

    cudaFuncSetAttribute(prep_all, cudaFuncAttributeMaxDynamicSharedMemorySize, PREP_SMEM);
    prep_all<<<1395, 512, PREP_SMEM>>>(q, S);          // #1

    cudaFuncSetAttribute(gemm_topk, cudaFuncAttributeMaxDynamicSharedMemorySize, SMEM_TOTAL);
    gemm_topk<<<dim3(7, 5, 75), 128, SMEM_TOTAL>>>();  // #2 (profiled)

    finalize_kernel<<<1, 512>>>(out);                  // #3
}